// round 5
// baseline (speedup 1.0000x reference)
#include <cuda_runtime.h>
#include <cuda_bf16.h>
#include <math.h>

// ---------------------------------------------------------------------------
// Problem constants
// ---------------------------------------------------------------------------
#define QLEN 1024
#define HID 3584
#define NH 28
#define NKV 4
#define HD 128
#define PAST 3072
#define KVLEN 4096          // PAST + QLEN
#define NREP 7              // NH / NKV

// ---------------------------------------------------------------------------
// Scratch (no allocations allowed -> __device__ globals)
// ---------------------------------------------------------------------------
__device__ float g_qp[QLEN * HID];          // raw Q proj  [1024][3584]
__device__ float g_kp[QLEN * NKV * HD];     // raw K proj  [1024][512]
__device__ float g_vp[QLEN * NKV * HD];     // raw V proj  [1024][512]
__device__ float g_qh[NH * QLEN * HD];      // roped Q, head-major [28][1024][128]
__device__ float g_kf[NKV * KVLEN * HD];    // full K [4][4096][128]
__device__ float g_vf[NKV * KVLEN * HD];    // full V [4][4096][128]
__device__ float g_attn[QLEN * HID];        // attention out [1024][3584]

// ---------------------------------------------------------------------------
// Generic 128x128x16 fp32 GEMM tile body. A: MxK row-major, B: KxN row-major.
// 256 threads, 8x8 micro-tile per thread.
// ---------------------------------------------------------------------------
__device__ __forceinline__ void gemm_body(const float* __restrict__ A,
                                          const float* __restrict__ B,
                                          const float* __restrict__ bias,
                                          float* __restrict__ C,
                                          int N, int K, int bm, int bn) {
    __shared__ float As[16][132];   // transposed A tile [k][m]
    __shared__ float Bs[16][132];   // B tile [k][n]

    const int tid = threadIdx.x;
    const int ty = tid >> 4;        // 0..15
    const int tx = tid & 15;        // 0..15

    const int arow = tid >> 2;          // 0..63
    const int acol = (tid & 3) * 4;     // 0,4,8,12
    const int brow = tid >> 5;          // 0..7
    const int bcol = (tid & 31) * 4;    // 0..124

    float acc[8][8];
#pragma unroll
    for (int i = 0; i < 8; i++)
#pragma unroll
        for (int j = 0; j < 8; j++) acc[i][j] = 0.f;

    for (int k0 = 0; k0 < K; k0 += 16) {
#pragma unroll
        for (int h = 0; h < 2; h++) {
            int r = arow + h * 64;
            float4 v = *(const float4*)&A[(size_t)(bm + r) * K + k0 + acol];
            As[acol + 0][r] = v.x;
            As[acol + 1][r] = v.y;
            As[acol + 2][r] = v.z;
            As[acol + 3][r] = v.w;
        }
#pragma unroll
        for (int h = 0; h < 2; h++) {
            int r = brow + h * 8;
            *(float4*)&Bs[r][bcol] =
                *(const float4*)&B[(size_t)(k0 + r) * N + bn + bcol];
        }
        __syncthreads();

#pragma unroll
        for (int kk = 0; kk < 16; kk++) {
            float4 a0 = *(const float4*)&As[kk][ty * 8];
            float4 a1 = *(const float4*)&As[kk][ty * 8 + 4];
            float4 b0 = *(const float4*)&Bs[kk][tx * 8];
            float4 b1 = *(const float4*)&Bs[kk][tx * 8 + 4];
            float a[8] = {a0.x, a0.y, a0.z, a0.w, a1.x, a1.y, a1.z, a1.w};
            float b[8] = {b0.x, b0.y, b0.z, b0.w, b1.x, b1.y, b1.z, b1.w};
#pragma unroll
            for (int i = 0; i < 8; i++)
#pragma unroll
                for (int j = 0; j < 8; j++) acc[i][j] = fmaf(a[i], b[j], acc[i][j]);
        }
        __syncthreads();
    }

#pragma unroll
    for (int i = 0; i < 8; i++) {
        int row = bm + ty * 8 + i;
#pragma unroll
        for (int j = 0; j < 8; j += 4) {
            int col = bn + tx * 8 + j;
            float4 v = make_float4(acc[i][j], acc[i][j + 1], acc[i][j + 2], acc[i][j + 3]);
            if (bias) {
                v.x += bias[col]; v.y += bias[col + 1];
                v.z += bias[col + 2]; v.w += bias[col + 3];
            }
            *(float4*)&C[(size_t)row * N + col] = v;
        }
    }
}

// Fused QKV projection: blockIdx.x<28 -> Q, [28,32) -> K, [32,36) -> V
__global__ __launch_bounds__(256) void qkv_gemm_kernel(
    const float* __restrict__ X,
    const float* __restrict__ Wq, const float* __restrict__ bq,
    const float* __restrict__ Wk, const float* __restrict__ bk,
    const float* __restrict__ Wv, const float* __restrict__ bv,
    float* __restrict__ Qo, float* __restrict__ Ko, float* __restrict__ Vo) {
    int bx = blockIdx.x;
    const float* W; const float* bias; float* C; int N; int bn;
    if (bx < 28)      { W = Wq; bias = bq; C = Qo; N = HID; bn = bx * 128; }
    else if (bx < 32) { W = Wk; bias = bk; C = Ko; N = NKV * HD; bn = (bx - 28) * 128; }
    else              { W = Wv; bias = bv; C = Vo; N = NKV * HD; bn = (bx - 32) * 128; }
    gemm_body(X, W, bias, C, N, HID, blockIdx.y * 128, bn);
}

// O-projection
__global__ __launch_bounds__(256) void out_gemm_kernel(
    const float* __restrict__ A, const float* __restrict__ Wo,
    float* __restrict__ C) {
    gemm_body(A, Wo, nullptr, C, HID, HID, blockIdx.y * 128, blockIdx.x * 128);
}

// ---------------------------------------------------------------------------
// Copy cached prefix into full KV buffers
// ---------------------------------------------------------------------------
__global__ void copy_cache_kernel(const float* __restrict__ kc,
                                  const float* __restrict__ vc,
                                  float* __restrict__ Kf,
                                  float* __restrict__ Vf) {
    const int per_h = PAST * HD / 4;  // float4 per kv head = 98304
    int i = blockIdx.x * blockDim.x + threadIdx.x;
    if (i >= NKV * per_h) return;
    int kh = i / per_h;
    int r = i - kh * per_h;
    const float4* ks = (const float4*)kc;
    const float4* vs = (const float4*)vc;
    float4* kd = (float4*)(Kf + (size_t)kh * KVLEN * HD);
    float4* vd = (float4*)(Vf + (size_t)kh * KVLEN * HD);
    kd[r] = ks[i];
    vd[r] = vs[i];
}

// ---------------------------------------------------------------------------
// RoPE + scatter. Q gets 1/sqrt(128) folded in. One block per token m.
// ---------------------------------------------------------------------------
__global__ void rope_kernel(const float* __restrict__ Qp,
                            const float* __restrict__ Kp,
                            const float* __restrict__ Vp,
                            const int* __restrict__ pos,
                            float* __restrict__ Qh,
                            float* __restrict__ Kf,
                            float* __restrict__ Vf) {
    const int m = blockIdx.x;
    const float p = (float)pos[m];
    const float qscale = 0.08838834764831845f;  // 1/sqrt(128)

    // Q heads: 28 heads x 64 rotation pairs
    for (int idx = threadIdx.x; idx < NH * 64; idx += blockDim.x) {
        int h = idx >> 6;
        int d = idx & 63;
        float invf = (float)exp(-(double)d * (1.3815510557964274e+01 / 64.0)); // ln(1e6)
        float ang = p * invf;
        float s, c;
        sincosf(ang, &s, &c);
        float x1 = Qp[(size_t)m * HID + h * HD + d];
        float x2 = Qp[(size_t)m * HID + h * HD + d + 64];
        float o1 = (x1 * c - x2 * s) * qscale;
        float o2 = (x2 * c + x1 * s) * qscale;
        float* dst = Qh + ((size_t)h * QLEN + m) * HD;
        dst[d] = o1;
        dst[d + 64] = o2;
    }
    // K (rope) + V (copy) for 4 kv heads
    for (int idx = threadIdx.x; idx < NKV * 64; idx += blockDim.x) {
        int kh = idx >> 6;
        int d = idx & 63;
        float invf = (float)exp(-(double)d * (1.3815510557964274e+01 / 64.0));
        float ang = p * invf;
        float s, c;
        sincosf(ang, &s, &c);
        float x1 = Kp[(size_t)m * (NKV * HD) + kh * HD + d];
        float x2 = Kp[(size_t)m * (NKV * HD) + kh * HD + d + 64];
        float* kd = Kf + ((size_t)kh * KVLEN + PAST + m) * HD;
        kd[d] = x1 * c - x2 * s;
        kd[d + 64] = x2 * c + x1 * s;
        float* vd = Vf + ((size_t)kh * KVLEN + PAST + m) * HD;
        vd[d] = Vp[(size_t)m * (NKV * HD) + kh * HD + d];
        vd[d + 64] = Vp[(size_t)m * (NKV * HD) + kh * HD + d + 64];
    }
}

// ---------------------------------------------------------------------------
// Flash attention, fp32. BQ=64, BKV=64, 256 threads.
// grid: (16 q-tiles, 28 heads). Dynamic smem ~118KB.
// smem layout (floats):
//   QsT [128][68]  (transposed Q tile, conflict-free LDS.128)
//   KsT [128][68]
//   Vs  [64][128]
//   Ps  [64][68]
//   rowm[64], rowl[64], rowsc[64]
// ---------------------------------------------------------------------------
#define ATTN_SMEM_FLOATS (128*68 + 128*68 + 64*128 + 64*68 + 192)

__global__ __launch_bounds__(256) void attn_kernel(
    const float* __restrict__ Qh, const float* __restrict__ Kf,
    const float* __restrict__ Vf, float* __restrict__ Aout) {
    extern __shared__ float sm[];
    float* QsT  = sm;
    float* KsT  = QsT + 128 * 68;
    float* Vs   = KsT + 128 * 68;
    float* Ps   = Vs + 64 * 128;
    float* rowm = Ps + 64 * 68;
    float* rowl = rowm + 64;
    float* rowsc = rowl + 64;

    const int tid = threadIdx.x;
    const int h = blockIdx.y;
    const int m0 = blockIdx.x * 64;
    const int kvh = h / NREP;
    const int ty = tid >> 4;
    const int tx = tid & 15;

    // ---- load Q tile transposed: QsT[d][r]
    {
        int d = tid & 127;
        int cgb = (tid >> 7) * 8;
        const float* qb = Qh + ((size_t)h * QLEN + m0) * HD + d;
#pragma unroll
        for (int i = 0; i < 8; i++) {
            int cg = cgb + i;
            float4 v;
            v.x = qb[(4 * cg + 0) * HD];
            v.y = qb[(4 * cg + 1) * HD];
            v.z = qb[(4 * cg + 2) * HD];
            v.w = qb[(4 * cg + 3) * HD];
            *(float4*)&QsT[d * 68 + 4 * cg] = v;
        }
    }
    if (tid < 64) { rowm[tid] = -1e30f; rowl[tid] = 0.f; }

    float o[4][8];
#pragma unroll
    for (int i = 0; i < 4; i++)
#pragma unroll
        for (int j = 0; j < 8; j++) o[i][j] = 0.f;

    __syncthreads();

    const int ntiles = 49 + blockIdx.x;  // covers kv 0 .. 3072+m0+63

    for (int t = 0; t < ntiles; t++) {
        // ---- load K tile transposed + V tile
        {
            int d = tid & 127;
            int cgb = (tid >> 7) * 8;
            const float* kb = Kf + ((size_t)kvh * KVLEN + t * 64) * HD + d;
#pragma unroll
            for (int i = 0; i < 8; i++) {
                int cg = cgb + i;
                float4 v;
                v.x = kb[(4 * cg + 0) * HD];
                v.y = kb[(4 * cg + 1) * HD];
                v.z = kb[(4 * cg + 2) * HD];
                v.w = kb[(4 * cg + 3) * HD];
                *(float4*)&KsT[d * 68 + 4 * cg] = v;
            }
            const float4* vb = (const float4*)(Vf + ((size_t)kvh * KVLEN + t * 64) * HD);
            float4* vs4 = (float4*)Vs;
#pragma unroll
            for (int i = 0; i < 8; i++) vs4[tid + i * 256] = vb[tid + i * 256];
        }
        __syncthreads();

        // ---- S = Q K^T (4x4 per thread)
        float s00=0,s01=0,s02=0,s03=0, s10=0,s11=0,s12=0,s13=0;
        float s20=0,s21=0,s22=0,s23=0, s30=0,s31=0,s32=0,s33=0;
        {
            const float* qp = QsT + 4 * ty;
            const float* kp = KsT + 4 * tx;
#pragma unroll 4
            for (int d = 0; d < 128; d++) {
                float4 a = *(const float4*)(qp + d * 68);
                float4 b = *(const float4*)(kp + d * 68);
                s00 = fmaf(a.x, b.x, s00); s01 = fmaf(a.x, b.y, s01);
                s02 = fmaf(a.x, b.z, s02); s03 = fmaf(a.x, b.w, s03);
                s10 = fmaf(a.y, b.x, s10); s11 = fmaf(a.y, b.y, s11);
                s12 = fmaf(a.y, b.z, s12); s13 = fmaf(a.y, b.w, s13);
                s20 = fmaf(a.z, b.x, s20); s21 = fmaf(a.z, b.y, s21);
                s22 = fmaf(a.z, b.z, s22); s23 = fmaf(a.z, b.w, s23);
                s30 = fmaf(a.w, b.x, s30); s31 = fmaf(a.w, b.y, s31);
                s32 = fmaf(a.w, b.z, s32); s33 = fmaf(a.w, b.w, s33);
            }
        }
        float s[4][4] = {{s00,s01,s02,s03},{s10,s11,s12,s13},
                         {s20,s21,s22,s23},{s30,s31,s32,s33}};

        // ---- causal mask (only last tile touches the diagonal)
        if (t == ntiles - 1) {
#pragma unroll
            for (int i = 0; i < 4; i++) {
                int lim = PAST + m0 + ty * 4 + i;
#pragma unroll
                for (int j = 0; j < 4; j++) {
                    int c = t * 64 + tx * 4 + j;
                    if (c > lim) s[i][j] = -1e30f;
                }
            }
        }

        // ---- online softmax (row groups live in a 16-lane shfl segment)
#pragma unroll
        for (int i = 0; i < 4; i++) {
            int r = ty * 4 + i;
            float tm = fmaxf(fmaxf(s[i][0], s[i][1]), fmaxf(s[i][2], s[i][3]));
            tm = fmaxf(tm, __shfl_xor_sync(0xffffffffu, tm, 1, 16));
            tm = fmaxf(tm, __shfl_xor_sync(0xffffffffu, tm, 2, 16));
            tm = fmaxf(tm, __shfl_xor_sync(0xffffffffu, tm, 4, 16));
            tm = fmaxf(tm, __shfl_xor_sync(0xffffffffu, tm, 8, 16));
            float mold = rowm[r];
            float mn = fmaxf(mold, tm);
            float su = 0.f;
#pragma unroll
            for (int j = 0; j < 4; j++) {
                float pj = __expf(s[i][j] - mn);
                s[i][j] = pj;
                su += pj;
            }
            su += __shfl_xor_sync(0xffffffffu, su, 1, 16);
            su += __shfl_xor_sync(0xffffffffu, su, 2, 16);
            su += __shfl_xor_sync(0xffffffffu, su, 4, 16);
            su += __shfl_xor_sync(0xffffffffu, su, 8, 16);
            if (tx == 0) {
                float fac = __expf(mold - mn);
                rowsc[r] = fac;
                rowl[r] = rowl[r] * fac + su;
                rowm[r] = mn;
            }
            *(float4*)&Ps[r * 68 + tx * 4] = make_float4(s[i][0], s[i][1], s[i][2], s[i][3]);
        }
        __syncthreads();

        // ---- O = O*scale + P @ V (4 rows x 8 cols per thread)
#pragma unroll
        for (int i = 0; i < 4; i++) {
            float sc = rowsc[ty * 4 + i];
#pragma unroll
            for (int j = 0; j < 8; j++) o[i][j] *= sc;
        }
#pragma unroll 2
        for (int jv = 0; jv < 64; jv++) {
            float p0 = Ps[(ty * 4 + 0) * 68 + jv];
            float p1 = Ps[(ty * 4 + 1) * 68 + jv];
            float p2 = Ps[(ty * 4 + 2) * 68 + jv];
            float p3 = Ps[(ty * 4 + 3) * 68 + jv];
            float4 v0 = *(const float4*)&Vs[jv * 128 + tx * 8];
            float4 v1 = *(const float4*)&Vs[jv * 128 + tx * 8 + 4];
            o[0][0] = fmaf(p0, v0.x, o[0][0]); o[0][1] = fmaf(p0, v0.y, o[0][1]);
            o[0][2] = fmaf(p0, v0.z, o[0][2]); o[0][3] = fmaf(p0, v0.w, o[0][3]);
            o[0][4] = fmaf(p0, v1.x, o[0][4]); o[0][5] = fmaf(p0, v1.y, o[0][5]);
            o[0][6] = fmaf(p0, v1.z, o[0][6]); o[0][7] = fmaf(p0, v1.w, o[0][7]);
            o[1][0] = fmaf(p1, v0.x, o[1][0]); o[1][1] = fmaf(p1, v0.y, o[1][1]);
            o[1][2] = fmaf(p1, v0.z, o[1][2]); o[1][3] = fmaf(p1, v0.w, o[1][3]);
            o[1][4] = fmaf(p1, v1.x, o[1][4]); o[1][5] = fmaf(p1, v1.y, o[1][5]);
            o[1][6] = fmaf(p1, v1.z, o[1][6]); o[1][7] = fmaf(p1, v1.w, o[1][7]);
            o[2][0] = fmaf(p2, v0.x, o[2][0]); o[2][1] = fmaf(p2, v0.y, o[2][1]);
            o[2][2] = fmaf(p2, v0.z, o[2][2]); o[2][3] = fmaf(p2, v0.w, o[2][3]);
            o[2][4] = fmaf(p2, v1.x, o[2][4]); o[2][5] = fmaf(p2, v1.y, o[2][5]);
            o[2][6] = fmaf(p2, v1.z, o[2][6]); o[2][7] = fmaf(p2, v1.w, o[2][7]);
            o[3][0] = fmaf(p3, v0.x, o[3][0]); o[3][1] = fmaf(p3, v0.y, o[3][1]);
            o[3][2] = fmaf(p3, v0.z, o[3][2]); o[3][3] = fmaf(p3, v0.w, o[3][3]);
            o[3][4] = fmaf(p3, v1.x, o[3][4]); o[3][5] = fmaf(p3, v1.y, o[3][5]);
            o[3][6] = fmaf(p3, v1.z, o[3][6]); o[3][7] = fmaf(p3, v1.w, o[3][7]);
        }
        __syncthreads();
    }

    // ---- normalize and write [1024][3584]
#pragma unroll
    for (int i = 0; i < 4; i++) {
        int r = ty * 4 + i;
        float inv = 1.0f / rowl[r];
        int row = m0 + r;
        float4 w0 = make_float4(o[i][0] * inv, o[i][1] * inv, o[i][2] * inv, o[i][3] * inv);
        float4 w1 = make_float4(o[i][4] * inv, o[i][5] * inv, o[i][6] * inv, o[i][7] * inv);
        *(float4*)&Aout[(size_t)row * HID + h * HD + tx * 8] = w0;
        *(float4*)&Aout[(size_t)row * HID + h * HD + tx * 8 + 4] = w1;
    }
}

// ---------------------------------------------------------------------------
// Launch
// ---------------------------------------------------------------------------
extern "C" void kernel_launch(void* const* d_in, const int* in_sizes, int n_in,
                              void* d_out, int out_size) {
    (void)in_sizes; (void)n_in; (void)out_size;
    const float* X  = (const float*)d_in[0];
    const float* kc = (const float*)d_in[1];
    const float* vc = (const float*)d_in[2];
    const float* Wq = (const float*)d_in[3];
    const float* bq = (const float*)d_in[4];
    const float* Wk = (const float*)d_in[5];
    const float* bk = (const float*)d_in[6];
    const float* Wv = (const float*)d_in[7];
    const float* bv = (const float*)d_in[8];
    const float* Wo = (const float*)d_in[9];
    const int*  pos = (const int*)d_in[10];
    float* out = (float*)d_out;

    float *qp, *kp, *vp, *qh, *kf, *vf, *attn;
    cudaGetSymbolAddress((void**)&qp, g_qp);
    cudaGetSymbolAddress((void**)&kp, g_kp);
    cudaGetSymbolAddress((void**)&vp, g_vp);
    cudaGetSymbolAddress((void**)&qh, g_qh);
    cudaGetSymbolAddress((void**)&kf, g_kf);
    cudaGetSymbolAddress((void**)&vf, g_vf);
    cudaGetSymbolAddress((void**)&attn, g_attn);

    // 1) fused QKV projection
    qkv_gemm_kernel<<<dim3(36, 8), 256>>>(X, Wq, bq, Wk, bk, Wv, bv, qp, kp, vp);

    // 2) KV cache prefix copy (independent of 1, same stream is fine)
    {
        int total = NKV * PAST * HD / 4;
        copy_cache_kernel<<<(total + 255) / 256, 256>>>(kc, vc, kf, vf);
    }

    // 3) RoPE + scatter into head-major / full-KV layouts
    rope_kernel<<<QLEN, 256>>>(qp, kp, vp, pos, qh, kf, vf);

    // 4) flash attention
    {
        const int smem_bytes = ATTN_SMEM_FLOATS * 4;
        cudaFuncSetAttribute(attn_kernel,
                             cudaFuncAttributeMaxDynamicSharedMemorySize, smem_bytes);
        attn_kernel<<<dim3(16, NH), 256, smem_bytes>>>(qh, kf, vf, attn);
    }

    // 5) output projection
    out_gemm_kernel<<<dim3(28, 8), 256>>>(attn, Wo, out);
}

// round 6
// speedup vs baseline: 1.8417x; 1.8417x over previous
#include <cuda_runtime.h>
#include <cuda_bf16.h>
#include <math.h>
#include <stdint.h>

// ---------------------------------------------------------------------------
// Problem constants
// ---------------------------------------------------------------------------
#define QLEN 1024
#define HID 3584
#define NH 28
#define NKV 4
#define HD 128
#define PAST 3072
#define KVLEN 4096          // PAST + QLEN
#define NREP 7              // NH / NKV

// ---------------------------------------------------------------------------
// Scratch (no allocations allowed -> __device__ globals)
// ---------------------------------------------------------------------------
__device__ float g_qp[QLEN * HID];          // raw Q proj  [1024][3584]
__device__ float g_kp[QLEN * NKV * HD];     // raw K proj  [1024][512]
__device__ float g_vp[QLEN * NKV * HD];     // raw V proj  [1024][512]
__device__ float g_qh[NH * QLEN * HD];      // roped Q (scaled), head-major [28][1024][128]
__device__ float g_kf[NKV * KVLEN * HD];    // full K [4][4096][128]
__device__ float g_vf[NKV * KVLEN * HD];    // full V [4][4096][128]
__device__ float g_attn[QLEN * HID];        // attention out [1024][3584]

// ---------------------------------------------------------------------------
// PTX helpers
// ---------------------------------------------------------------------------
__device__ __forceinline__ unsigned f2tf32(float x) {
    unsigned r;
    asm("cvt.rna.tf32.f32 %0, %1;" : "=r"(r) : "f"(x));
    return r;
}
__device__ __forceinline__ void splitf(float x, unsigned& hi, unsigned& lo) {
    hi = f2tf32(x);
    lo = f2tf32(x - __uint_as_float(hi));
}
__device__ __forceinline__ void mma8(float* d, const unsigned* a, const unsigned* b) {
    asm volatile(
        "mma.sync.aligned.m16n8k8.row.col.f32.tf32.tf32.f32 "
        "{%0,%1,%2,%3}, {%4,%5,%6,%7}, {%8,%9}, {%0,%1,%2,%3};\n"
        : "+f"(d[0]), "+f"(d[1]), "+f"(d[2]), "+f"(d[3])
        : "r"(a[0]), "r"(a[1]), "r"(a[2]), "r"(a[3]), "r"(b[0]), "r"(b[1]));
}
__device__ __forceinline__ void cp16(const float* smem_dst, const float* gmem_src) {
    unsigned s = (unsigned)__cvta_generic_to_shared(smem_dst);
    asm volatile("cp.async.cg.shared.global [%0], [%1], 16;\n"
                 :: "r"(s), "l"(__cvta_generic_to_global(gmem_src)));
}
#define CP_COMMIT() asm volatile("cp.async.commit_group;\n")
#define CP_WAIT0()  asm volatile("cp.async.wait_group 0;\n")

// ---------------------------------------------------------------------------
// tf32 GEMM: 128x128 tile, BK=32, 256 threads (8 warps, 4x2), double-buffered
// cp.async. SPLIT=3 -> tf32x3 (near-fp32 accuracy); SPLIT=1 -> single tf32.
// A: MxK row-major, B: KxN row-major, C row-major.
// ---------------------------------------------------------------------------
#define AS_STR 36
#define BS_STR 136
#define AS_BUF (128 * AS_STR)
#define BS_BUF (32 * BS_STR)
#define GEMM_SMEM_BYTES ((2 * AS_BUF + 2 * BS_BUF) * 4)

template <int SPLIT>
__device__ __forceinline__ void gemm_tf32(const float* __restrict__ A,
                                          const float* __restrict__ B,
                                          const float* __restrict__ bias,
                                          float* __restrict__ C,
                                          int N, int K, int bm, int bn) {
    extern __shared__ float sm[];
    float* AS = sm;
    float* BS = sm + 2 * AS_BUF;

    const int tid = threadIdx.x;
    const int lane = tid & 31;
    const int wid = tid >> 5;
    const int wm = (wid >> 1) * 32;
    const int wn = (wid & 1) * 64;
    const int g = lane >> 2;
    const int c = lane & 3;

    float acc[2][8][4];
#pragma unroll
    for (int mt = 0; mt < 2; mt++)
#pragma unroll
        for (int nt = 0; nt < 8; nt++)
#pragma unroll
            for (int j = 0; j < 4; j++) acc[mt][nt][j] = 0.f;

    const int nk = K / 32;

    // prefetch tile 0
    {
        float* as = AS;
        float* bs = BS;
#pragma unroll
        for (int i = 0; i < 4; i++) {
            int idx = tid + i * 256;
            int r = idx >> 3, cc = (idx & 7) * 4;
            cp16(&as[r * AS_STR + cc], &A[(size_t)(bm + r) * K + cc]);
        }
#pragma unroll
        for (int i = 0; i < 4; i++) {
            int idx = tid + i * 256;
            int r = idx >> 5, cc = (idx & 31) * 4;
            cp16(&bs[r * BS_STR + cc], &B[(size_t)r * N + bn + cc]);
        }
        CP_COMMIT();
    }

    for (int it = 0; it < nk; it++) {
        CP_WAIT0();
        __syncthreads();
        if (it + 1 < nk) {
            int k0 = (it + 1) * 32;
            float* as = AS + ((it + 1) & 1) * AS_BUF;
            float* bs = BS + ((it + 1) & 1) * BS_BUF;
#pragma unroll
            for (int i = 0; i < 4; i++) {
                int idx = tid + i * 256;
                int r = idx >> 3, cc = (idx & 7) * 4;
                cp16(&as[r * AS_STR + cc], &A[(size_t)(bm + r) * K + k0 + cc]);
            }
#pragma unroll
            for (int i = 0; i < 4; i++) {
                int idx = tid + i * 256;
                int r = idx >> 5, cc = (idx & 31) * 4;
                cp16(&bs[r * BS_STR + cc], &B[(size_t)(k0 + r) * N + bn + cc]);
            }
            CP_COMMIT();
        }
        const float* as = AS + (it & 1) * AS_BUF;
        const float* bs = BS + (it & 1) * BS_BUF;

#pragma unroll
        for (int kt = 0; kt < 4; kt++) {
            unsigned ah[2][4], al[2][4];
#pragma unroll
            for (int mt = 0; mt < 2; mt++) {
                int rb = wm + mt * 16;
                float f0 = as[(rb + g) * AS_STR + kt * 8 + c];
                float f1 = as[(rb + g + 8) * AS_STR + kt * 8 + c];
                float f2 = as[(rb + g) * AS_STR + kt * 8 + c + 4];
                float f3 = as[(rb + g + 8) * AS_STR + kt * 8 + c + 4];
                if (SPLIT == 3) {
                    splitf(f0, ah[mt][0], al[mt][0]);
                    splitf(f1, ah[mt][1], al[mt][1]);
                    splitf(f2, ah[mt][2], al[mt][2]);
                    splitf(f3, ah[mt][3], al[mt][3]);
                } else {
                    ah[mt][0] = f2tf32(f0); ah[mt][1] = f2tf32(f1);
                    ah[mt][2] = f2tf32(f2); ah[mt][3] = f2tf32(f3);
                }
            }
#pragma unroll
            for (int nt = 0; nt < 8; nt++) {
                float f0 = bs[(kt * 8 + c) * BS_STR + wn + nt * 8 + g];
                float f1 = bs[(kt * 8 + c + 4) * BS_STR + wn + nt * 8 + g];
                unsigned bh[2], bl[2];
                if (SPLIT == 3) {
                    splitf(f0, bh[0], bl[0]);
                    splitf(f1, bh[1], bl[1]);
                } else {
                    bh[0] = f2tf32(f0); bh[1] = f2tf32(f1);
                }
#pragma unroll
                for (int mt = 0; mt < 2; mt++) {
                    mma8(acc[mt][nt], ah[mt], bh);
                    if (SPLIT == 3) {
                        mma8(acc[mt][nt], al[mt], bh);
                        mma8(acc[mt][nt], ah[mt], bl);
                    }
                }
            }
        }
    }

    // epilogue
#pragma unroll
    for (int mt = 0; mt < 2; mt++) {
        int r0 = bm + wm + mt * 16 + g;
#pragma unroll
        for (int nt = 0; nt < 8; nt++) {
            int c0 = bn + wn + nt * 8 + 2 * c;
            float2 v0 = make_float2(acc[mt][nt][0], acc[mt][nt][1]);
            float2 v1 = make_float2(acc[mt][nt][2], acc[mt][nt][3]);
            if (bias) {
                float b0 = bias[c0], b1 = bias[c0 + 1];
                v0.x += b0; v0.y += b1;
                v1.x += b0; v1.y += b1;
            }
            *(float2*)&C[(size_t)r0 * N + c0] = v0;
            *(float2*)&C[(size_t)(r0 + 8) * N + c0] = v1;
        }
    }
}

// Fused QKV projection (tf32x3): blockIdx.x<28 -> Q, [28,32) -> K, [32,36) -> V
__global__ __launch_bounds__(256, 2) void qkv_gemm_kernel(
    const float* __restrict__ X,
    const float* __restrict__ Wq, const float* __restrict__ bq,
    const float* __restrict__ Wk, const float* __restrict__ bk,
    const float* __restrict__ Wv, const float* __restrict__ bv,
    float* __restrict__ Qo, float* __restrict__ Ko, float* __restrict__ Vo) {
    int bx = blockIdx.x;
    const float* W; const float* bias; float* C; int N; int bn;
    if (bx < 28)      { W = Wq; bias = bq; C = Qo; N = HID; bn = bx * 128; }
    else if (bx < 32) { W = Wk; bias = bk; C = Ko; N = NKV * HD; bn = (bx - 28) * 128; }
    else              { W = Wv; bias = bv; C = Vo; N = NKV * HD; bn = (bx - 32) * 128; }
    gemm_tf32<3>(X, W, bias, C, N, HID, blockIdx.y * 128, bn);
}

// O-projection (single tf32)
__global__ __launch_bounds__(256, 2) void out_gemm_kernel(
    const float* __restrict__ A, const float* __restrict__ Wo,
    float* __restrict__ C) {
    gemm_tf32<1>(A, Wo, nullptr, C, HID, HID, blockIdx.y * 128, blockIdx.x * 128);
}

// ---------------------------------------------------------------------------
// Copy cached prefix into full KV buffers
// ---------------------------------------------------------------------------
__global__ void copy_cache_kernel(const float* __restrict__ kc,
                                  const float* __restrict__ vc,
                                  float* __restrict__ Kf,
                                  float* __restrict__ Vf) {
    const int per_h = PAST * HD / 4;
    int i = blockIdx.x * blockDim.x + threadIdx.x;
    if (i >= NKV * per_h) return;
    int kh = i / per_h;
    int r = i - kh * per_h;
    const float4* ks = (const float4*)kc;
    const float4* vs = (const float4*)vc;
    float4* kd = (float4*)(Kf + (size_t)kh * KVLEN * HD);
    float4* vd = (float4*)(Vf + (size_t)kh * KVLEN * HD);
    kd[r] = ks[i];
    vd[r] = vs[i];
}

// ---------------------------------------------------------------------------
// RoPE + scatter. Q gets 1/sqrt(128) folded in. One block per token m.
// ---------------------------------------------------------------------------
__global__ void rope_kernel(const float* __restrict__ Qp,
                            const float* __restrict__ Kp,
                            const float* __restrict__ Vp,
                            const int* __restrict__ pos,
                            float* __restrict__ Qh,
                            float* __restrict__ Kf,
                            float* __restrict__ Vf) {
    const int m = blockIdx.x;
    const float p = (float)pos[m];
    const float qscale = 0.08838834764831845f;  // 1/sqrt(128)

    for (int idx = threadIdx.x; idx < NH * 64; idx += blockDim.x) {
        int h = idx >> 6;
        int d = idx & 63;
        float invf = (float)exp(-(double)d * (1.3815510557964274e+01 / 64.0));
        float ang = p * invf;
        float s, c;
        sincosf(ang, &s, &c);
        float x1 = Qp[(size_t)m * HID + h * HD + d];
        float x2 = Qp[(size_t)m * HID + h * HD + d + 64];
        float o1 = (x1 * c - x2 * s) * qscale;
        float o2 = (x2 * c + x1 * s) * qscale;
        float* dst = Qh + ((size_t)h * QLEN + m) * HD;
        dst[d] = o1;
        dst[d + 64] = o2;
    }
    for (int idx = threadIdx.x; idx < NKV * 64; idx += blockDim.x) {
        int kh = idx >> 6;
        int d = idx & 63;
        float invf = (float)exp(-(double)d * (1.3815510557964274e+01 / 64.0));
        float ang = p * invf;
        float s, c;
        sincosf(ang, &s, &c);
        float x1 = Kp[(size_t)m * (NKV * HD) + kh * HD + d];
        float x2 = Kp[(size_t)m * (NKV * HD) + kh * HD + d + 64];
        float* kd = Kf + ((size_t)kh * KVLEN + PAST + m) * HD;
        kd[d] = x1 * c - x2 * s;
        kd[d + 64] = x2 * c + x1 * s;
        float* vd = Vf + ((size_t)kh * KVLEN + PAST + m) * HD;
        vd[d] = Vp[(size_t)m * (NKV * HD) + kh * HD + d];
        vd[d + 64] = Vp[(size_t)m * (NKV * HD) + kh * HD + d + 64];
    }
}

// ---------------------------------------------------------------------------
// Flash attention, tf32 tensor-core. BQ=128, BKV=64, 256 threads (8 warps,
// each warp owns 16 q-rows). S=QK^T uses tf32x3 (logit accuracy), P.V single
// tf32. Q persistent in smem; K/V register-prefetched per tile.
// grid: (8 q-tiles, 28 heads). smem = 171,008 B.
// ---------------------------------------------------------------------------
#define QS_STR 132
#define KS_STR 132
#define VS_STR 136
#define PS_STR 68
#define QS_FLOATS (128 * QS_STR)
#define KS_FLOATS (64 * KS_STR)
#define VS_FLOATS (64 * VS_STR)
#define PS_FLOATS (128 * PS_STR)
#define ATTN_SMEM_BYTES ((QS_FLOATS + KS_FLOATS + VS_FLOATS + PS_FLOATS) * 4)

__global__ __launch_bounds__(256, 1) void attn_kernel(
    const float* __restrict__ Qh, const float* __restrict__ Kf,
    const float* __restrict__ Vf, float* __restrict__ Aout) {
    extern __shared__ float sm[];
    float* QS = sm;
    float* KS = QS + QS_FLOATS;
    float* VS = KS + KS_FLOATS;
    float* PS = VS + VS_FLOATS;

    const int tid = threadIdx.x;
    const int lane = tid & 31;
    const int w = tid >> 5;       // 8 warps
    const int g = lane >> 2;      // 0..7
    const int c = lane & 3;       // 0..3
    const int h = blockIdx.y;
    const int m0 = blockIdx.x * 128;
    const int kvh = h / NREP;

    // ---- prologue: load Q tile [128][128] into QS (fp32, persists)
    {
        const float4* qb = (const float4*)(Qh + ((size_t)h * QLEN + m0) * HD);
#pragma unroll
        for (int i = 0; i < 16; i++) {
            int idx = tid + i * 256;
            int r = idx >> 5, c4 = idx & 31;
            *(float4*)&QS[r * QS_STR + c4 * 4] = qb[idx];
        }
    }
    __syncthreads();

    const int ntiles = 48 + 2 * blockIdx.x + 2;

    // per-row online softmax state (replicated across the 4 lanes of a group)
    float mrow[2] = {-1e30f, -1e30f};
    float lrow[2] = {0.f, 0.f};
    float o[16][4];
#pragma unroll
    for (int dt = 0; dt < 16; dt++)
#pragma unroll
        for (int j = 0; j < 4; j++) o[dt][j] = 0.f;

    // register prefetch of tile 0
    float4 kq[8], vq[8];
    {
        const float4* kb = (const float4*)(Kf + ((size_t)kvh * KVLEN) * HD);
        const float4* vb = (const float4*)(Vf + ((size_t)kvh * KVLEN) * HD);
#pragma unroll
        for (int i = 0; i < 8; i++) { kq[i] = kb[tid + i * 256]; vq[i] = vb[tid + i * 256]; }
    }

    for (int t = 0; t < ntiles; t++) {
        __syncthreads();   // all readers of previous K/V tile done
        // store prefetched tile to smem
#pragma unroll
        for (int i = 0; i < 8; i++) {
            int idx = tid + i * 256;
            int r = idx >> 5, c4 = idx & 31;
            *(float4*)&KS[r * KS_STR + c4 * 4] = kq[i];
            *(float4*)&VS[r * VS_STR + c4 * 4] = vq[i];
        }
        __syncthreads();
        // issue prefetch of next tile (hidden under the MMA work below)
        if (t + 1 < ntiles) {
            const float4* kb = (const float4*)(Kf + ((size_t)kvh * KVLEN + (t + 1) * 64) * HD);
            const float4* vb = (const float4*)(Vf + ((size_t)kvh * KVLEN + (t + 1) * 64) * HD);
#pragma unroll
            for (int i = 0; i < 8; i++) { kq[i] = kb[tid + i * 256]; vq[i] = vb[tid + i * 256]; }
        }

        // ---- S = Q K^T (tf32x3), per warp: 16 x 64
        float s[8][4];
#pragma unroll
        for (int nt = 0; nt < 8; nt++)
#pragma unroll
            for (int j = 0; j < 4; j++) s[nt][j] = 0.f;

        const float* QSw = QS + (w * 16) * QS_STR;
#pragma unroll 2
        for (int kt = 0; kt < 16; kt++) {
            unsigned ah[4], al[4];
            splitf(QSw[g * QS_STR + kt * 8 + c],            ah[0], al[0]);
            splitf(QSw[(g + 8) * QS_STR + kt * 8 + c],      ah[1], al[1]);
            splitf(QSw[g * QS_STR + kt * 8 + c + 4],        ah[2], al[2]);
            splitf(QSw[(g + 8) * QS_STR + kt * 8 + c + 4],  ah[3], al[3]);
#pragma unroll
            for (int nt = 0; nt < 8; nt++) {
                unsigned bh[2], bl[2];
                splitf(KS[(nt * 8 + g) * KS_STR + kt * 8 + c],     bh[0], bl[0]);
                splitf(KS[(nt * 8 + g) * KS_STR + kt * 8 + c + 4], bh[1], bl[1]);
                mma8(s[nt], ah, bh);
                mma8(s[nt], al, bh);
                mma8(s[nt], ah, bl);
            }
        }

        // ---- causal mask (only last two tiles touch the diagonal)
        if (t >= ntiles - 2) {
            int base_col = t * 64;
            int lim0 = PAST + m0 + w * 16 + g;
            int lim1 = lim0 + 8;
#pragma unroll
            for (int nt = 0; nt < 8; nt++) {
                int c0 = base_col + nt * 8 + 2 * c;
                if (c0 > lim0)     s[nt][0] = -1e30f;
                if (c0 + 1 > lim0) s[nt][1] = -1e30f;
                if (c0 > lim1)     s[nt][2] = -1e30f;
                if (c0 + 1 > lim1) s[nt][3] = -1e30f;
            }
        }

        // ---- online softmax (rows g and g+8; reductions over the 4-lane group)
#pragma unroll
        for (int rr = 0; rr < 2; rr++) {
            float mx = -1e30f;
#pragma unroll
            for (int nt = 0; nt < 8; nt++)
                mx = fmaxf(mx, fmaxf(s[nt][2 * rr], s[nt][2 * rr + 1]));
            mx = fmaxf(mx, __shfl_xor_sync(0xffffffffu, mx, 1));
            mx = fmaxf(mx, __shfl_xor_sync(0xffffffffu, mx, 2));
            float mn = fmaxf(mrow[rr], mx);
            float alpha = __expf(mrow[rr] - mn);
            mrow[rr] = mn;
            float ls = 0.f;
#pragma unroll
            for (int nt = 0; nt < 8; nt++) {
                float e0 = __expf(s[nt][2 * rr] - mn);
                float e1 = __expf(s[nt][2 * rr + 1] - mn);
                s[nt][2 * rr] = e0;
                s[nt][2 * rr + 1] = e1;
                ls += e0 + e1;
            }
            ls += __shfl_xor_sync(0xffffffffu, ls, 1);
            ls += __shfl_xor_sync(0xffffffffu, ls, 2);
            lrow[rr] = lrow[rr] * alpha + ls;
#pragma unroll
            for (int dt = 0; dt < 16; dt++) {
                o[dt][2 * rr] *= alpha;
                o[dt][2 * rr + 1] *= alpha;
            }
        }

        // ---- store P to smem as tf32 bit-patterns (A-frag layout friendly)
        {
            float* p0 = PS + (w * 16 + g) * PS_STR;
            float* p1 = PS + (w * 16 + g + 8) * PS_STR;
#pragma unroll
            for (int nt = 0; nt < 8; nt++) {
                *(float2*)&p0[nt * 8 + 2 * c] = make_float2(
                    __uint_as_float(f2tf32(s[nt][0])), __uint_as_float(f2tf32(s[nt][1])));
                *(float2*)&p1[nt * 8 + 2 * c] = make_float2(
                    __uint_as_float(f2tf32(s[nt][2])), __uint_as_float(f2tf32(s[nt][3])));
            }
        }
        __syncwarp();

        // ---- O += P @ V (single tf32), per warp: 16 x 128
        const float* PSw = PS + (w * 16) * PS_STR;
#pragma unroll
        for (int ktv = 0; ktv < 8; ktv++) {
            unsigned a[4];
            a[0] = __float_as_uint(PSw[g * PS_STR + ktv * 8 + c]);
            a[1] = __float_as_uint(PSw[(g + 8) * PS_STR + ktv * 8 + c]);
            a[2] = __float_as_uint(PSw[g * PS_STR + ktv * 8 + c + 4]);
            a[3] = __float_as_uint(PSw[(g + 8) * PS_STR + ktv * 8 + c + 4]);
#pragma unroll
            for (int dt = 0; dt < 16; dt++) {
                unsigned b[2];
                b[0] = f2tf32(VS[(ktv * 8 + c) * VS_STR + dt * 8 + g]);
                b[1] = f2tf32(VS[(ktv * 8 + c + 4) * VS_STR + dt * 8 + g]);
                mma8(o[dt], a, b);
            }
        }
    }

    // ---- normalize and write [1024][3584]
#pragma unroll
    for (int rr = 0; rr < 2; rr++) {
        float inv = 1.0f / lrow[rr];
        int row = m0 + w * 16 + g + rr * 8;
        float* dst = Aout + (size_t)row * HID + h * HD;
#pragma unroll
        for (int dt = 0; dt < 16; dt++) {
            *(float2*)&dst[dt * 8 + 2 * c] =
                make_float2(o[dt][2 * rr] * inv, o[dt][2 * rr + 1] * inv);
        }
    }
}

// ---------------------------------------------------------------------------
// Launch
// ---------------------------------------------------------------------------
extern "C" void kernel_launch(void* const* d_in, const int* in_sizes, int n_in,
                              void* d_out, int out_size) {
    (void)in_sizes; (void)n_in; (void)out_size;
    const float* X  = (const float*)d_in[0];
    const float* kc = (const float*)d_in[1];
    const float* vc = (const float*)d_in[2];
    const float* Wq = (const float*)d_in[3];
    const float* bq = (const float*)d_in[4];
    const float* Wk = (const float*)d_in[5];
    const float* bk = (const float*)d_in[6];
    const float* Wv = (const float*)d_in[7];
    const float* bv = (const float*)d_in[8];
    const float* Wo = (const float*)d_in[9];
    const int*  pos = (const int*)d_in[10];
    float* out = (float*)d_out;

    float *qp, *kp, *vp, *qh, *kf, *vf, *attn;
    cudaGetSymbolAddress((void**)&qp, g_qp);
    cudaGetSymbolAddress((void**)&kp, g_kp);
    cudaGetSymbolAddress((void**)&vp, g_vp);
    cudaGetSymbolAddress((void**)&qh, g_qh);
    cudaGetSymbolAddress((void**)&kf, g_kf);
    cudaGetSymbolAddress((void**)&vf, g_vf);
    cudaGetSymbolAddress((void**)&attn, g_attn);

    static bool attr_set = false;
    if (!attr_set) {
        cudaFuncSetAttribute(qkv_gemm_kernel,
                             cudaFuncAttributeMaxDynamicSharedMemorySize, GEMM_SMEM_BYTES);
        cudaFuncSetAttribute(out_gemm_kernel,
                             cudaFuncAttributeMaxDynamicSharedMemorySize, GEMM_SMEM_BYTES);
        cudaFuncSetAttribute(attn_kernel,
                             cudaFuncAttributeMaxDynamicSharedMemorySize, ATTN_SMEM_BYTES);
        attr_set = true;
    }

    // 1) fused QKV projection (tf32x3 tensor-core)
    qkv_gemm_kernel<<<dim3(36, 8), 256, GEMM_SMEM_BYTES>>>(
        X, Wq, bq, Wk, bk, Wv, bv, qp, kp, vp);

    // 2) KV cache prefix copy
    {
        int total = NKV * PAST * HD / 4;
        copy_cache_kernel<<<(total + 255) / 256, 256>>>(kc, vc, kf, vf);
    }

    // 3) RoPE + scatter into head-major / full-KV layouts
    rope_kernel<<<QLEN, 256>>>(qp, kp, vp, pos, qh, kf, vf);

    // 4) flash attention (tensor-core)
    attn_kernel<<<dim3(8, NH), 256, ATTN_SMEM_BYTES>>>(qh, kf, vf, attn);

    // 5) output projection (single tf32)
    out_gemm_kernel<<<dim3(28, 8), 256, GEMM_SMEM_BYTES>>>(attn, Wo, out);
}

// round 7
// speedup vs baseline: 2.0230x; 1.0984x over previous
#include <cuda_runtime.h>
#include <cuda_bf16.h>
#include <math.h>
#include <stdint.h>

// ---------------------------------------------------------------------------
// Problem constants
// ---------------------------------------------------------------------------
#define QLEN 1024
#define HID 3584
#define NH 28
#define NKV 4
#define HD 128
#define PAST 3072
#define KVLEN 4096          // PAST + QLEN
#define NREP 7              // NH / NKV

// ---------------------------------------------------------------------------
// Scratch (no allocations allowed -> __device__ globals)
// ---------------------------------------------------------------------------
__device__ float g_qp[QLEN * HID];          // raw Q proj  [1024][3584]
__device__ float g_kp[QLEN * NKV * HD];     // raw K proj  [1024][512]
__device__ float g_vp[QLEN * NKV * HD];     // raw V proj  [1024][512]
__device__ float g_qh[NH * QLEN * HD];      // roped Q (scaled), head-major [28][1024][128]
__device__ float g_kf[NKV * KVLEN * HD];    // full K [4][4096][128]
__device__ float g_vf[NKV * KVLEN * HD];    // full V [4][4096][128]
__device__ float g_attn[QLEN * HID];        // attention out [1024][3584]

// ---------------------------------------------------------------------------
// PTX helpers
// ---------------------------------------------------------------------------
__device__ __forceinline__ unsigned f2tf32(float x) {
    unsigned r;
    asm("cvt.rna.tf32.f32 %0, %1;" : "=r"(r) : "f"(x));
    return r;
}
__device__ __forceinline__ void splitf(float x, unsigned& hi, unsigned& lo) {
    hi = f2tf32(x);
    lo = f2tf32(x - __uint_as_float(hi));
}
__device__ __forceinline__ void mma8(float* d, const unsigned* a, const unsigned* b) {
    asm volatile(
        "mma.sync.aligned.m16n8k8.row.col.f32.tf32.tf32.f32 "
        "{%0,%1,%2,%3}, {%4,%5,%6,%7}, {%8,%9}, {%0,%1,%2,%3};\n"
        : "+f"(d[0]), "+f"(d[1]), "+f"(d[2]), "+f"(d[3])
        : "r"(a[0]), "r"(a[1]), "r"(a[2]), "r"(a[3]), "r"(b[0]), "r"(b[1]));
}
__device__ __forceinline__ void cp16(const float* smem_dst, const float* gmem_src) {
    unsigned s = (unsigned)__cvta_generic_to_shared(smem_dst);
    asm volatile("cp.async.cg.shared.global [%0], [%1], 16;\n"
                 :: "r"(s), "l"(__cvta_generic_to_global(gmem_src)));
}
#define CP_COMMIT() asm volatile("cp.async.commit_group;\n")
#define CP_WAIT0()  asm volatile("cp.async.wait_group 0;\n")

// ---------------------------------------------------------------------------
// tf32 GEMM: 128x128 tile, BK=32, 256 threads (8 warps, 4x2), double-buffered
// cp.async. SPLIT=3 -> tf32x3 (near-fp32 accuracy); SPLIT=1 -> single tf32.
// A: MxK row-major, B: KxN row-major, C row-major.  (unchanged from R6)
// ---------------------------------------------------------------------------
#define AS_STR 36
#define BS_STR 136
#define AS_BUF (128 * AS_STR)
#define BS_BUF (32 * BS_STR)
#define GEMM_SMEM_BYTES ((2 * AS_BUF + 2 * BS_BUF) * 4)

template <int SPLIT>
__device__ __forceinline__ void gemm_tf32(const float* __restrict__ A,
                                          const float* __restrict__ B,
                                          const float* __restrict__ bias,
                                          float* __restrict__ C,
                                          int N, int K, int bm, int bn) {
    extern __shared__ float sm[];
    float* AS = sm;
    float* BS = sm + 2 * AS_BUF;

    const int tid = threadIdx.x;
    const int lane = tid & 31;
    const int wid = tid >> 5;
    const int wm = (wid >> 1) * 32;
    const int wn = (wid & 1) * 64;
    const int g = lane >> 2;
    const int c = lane & 3;

    float acc[2][8][4];
#pragma unroll
    for (int mt = 0; mt < 2; mt++)
#pragma unroll
        for (int nt = 0; nt < 8; nt++)
#pragma unroll
            for (int j = 0; j < 4; j++) acc[mt][nt][j] = 0.f;

    const int nk = K / 32;

    // prefetch tile 0
    {
        float* as = AS;
        float* bs = BS;
#pragma unroll
        for (int i = 0; i < 4; i++) {
            int idx = tid + i * 256;
            int r = idx >> 3, cc = (idx & 7) * 4;
            cp16(&as[r * AS_STR + cc], &A[(size_t)(bm + r) * K + cc]);
        }
#pragma unroll
        for (int i = 0; i < 4; i++) {
            int idx = tid + i * 256;
            int r = idx >> 5, cc = (idx & 31) * 4;
            cp16(&bs[r * BS_STR + cc], &B[(size_t)r * N + bn + cc]);
        }
        CP_COMMIT();
    }

    for (int it = 0; it < nk; it++) {
        CP_WAIT0();
        __syncthreads();
        if (it + 1 < nk) {
            int k0 = (it + 1) * 32;
            float* as = AS + ((it + 1) & 1) * AS_BUF;
            float* bs = BS + ((it + 1) & 1) * BS_BUF;
#pragma unroll
            for (int i = 0; i < 4; i++) {
                int idx = tid + i * 256;
                int r = idx >> 3, cc = (idx & 7) * 4;
                cp16(&as[r * AS_STR + cc], &A[(size_t)(bm + r) * K + k0 + cc]);
            }
#pragma unroll
            for (int i = 0; i < 4; i++) {
                int idx = tid + i * 256;
                int r = idx >> 5, cc = (idx & 31) * 4;
                cp16(&bs[r * BS_STR + cc], &B[(size_t)(k0 + r) * N + bn + cc]);
            }
            CP_COMMIT();
        }
        const float* as = AS + (it & 1) * AS_BUF;
        const float* bs = BS + (it & 1) * BS_BUF;

#pragma unroll
        for (int kt = 0; kt < 4; kt++) {
            unsigned ah[2][4], al[2][4];
#pragma unroll
            for (int mt = 0; mt < 2; mt++) {
                int rb = wm + mt * 16;
                float f0 = as[(rb + g) * AS_STR + kt * 8 + c];
                float f1 = as[(rb + g + 8) * AS_STR + kt * 8 + c];
                float f2 = as[(rb + g) * AS_STR + kt * 8 + c + 4];
                float f3 = as[(rb + g + 8) * AS_STR + kt * 8 + c + 4];
                if (SPLIT == 3) {
                    splitf(f0, ah[mt][0], al[mt][0]);
                    splitf(f1, ah[mt][1], al[mt][1]);
                    splitf(f2, ah[mt][2], al[mt][2]);
                    splitf(f3, ah[mt][3], al[mt][3]);
                } else {
                    ah[mt][0] = f2tf32(f0); ah[mt][1] = f2tf32(f1);
                    ah[mt][2] = f2tf32(f2); ah[mt][3] = f2tf32(f3);
                }
            }
#pragma unroll
            for (int nt = 0; nt < 8; nt++) {
                float f0 = bs[(kt * 8 + c) * BS_STR + wn + nt * 8 + g];
                float f1 = bs[(kt * 8 + c + 4) * BS_STR + wn + nt * 8 + g];
                unsigned bh[2], bl[2];
                if (SPLIT == 3) {
                    splitf(f0, bh[0], bl[0]);
                    splitf(f1, bh[1], bl[1]);
                } else {
                    bh[0] = f2tf32(f0); bh[1] = f2tf32(f1);
                }
#pragma unroll
                for (int mt = 0; mt < 2; mt++) {
                    mma8(acc[mt][nt], ah[mt], bh);
                    if (SPLIT == 3) {
                        mma8(acc[mt][nt], al[mt], bh);
                        mma8(acc[mt][nt], ah[mt], bl);
                    }
                }
            }
        }
    }

    // epilogue
#pragma unroll
    for (int mt = 0; mt < 2; mt++) {
        int r0 = bm + wm + mt * 16 + g;
#pragma unroll
        for (int nt = 0; nt < 8; nt++) {
            int c0 = bn + wn + nt * 8 + 2 * c;
            float2 v0 = make_float2(acc[mt][nt][0], acc[mt][nt][1]);
            float2 v1 = make_float2(acc[mt][nt][2], acc[mt][nt][3]);
            if (bias) {
                float b0 = bias[c0], b1 = bias[c0 + 1];
                v0.x += b0; v0.y += b1;
                v1.x += b0; v1.y += b1;
            }
            *(float2*)&C[(size_t)r0 * N + c0] = v0;
            *(float2*)&C[(size_t)(r0 + 8) * N + c0] = v1;
        }
    }
}

// Fused QKV projection (tf32x3): blockIdx.x<28 -> Q, [28,32) -> K, [32,36) -> V
__global__ __launch_bounds__(256, 2) void qkv_gemm_kernel(
    const float* __restrict__ X,
    const float* __restrict__ Wq, const float* __restrict__ bq,
    const float* __restrict__ Wk, const float* __restrict__ bk,
    const float* __restrict__ Wv, const float* __restrict__ bv,
    float* __restrict__ Qo, float* __restrict__ Ko, float* __restrict__ Vo) {
    int bx = blockIdx.x;
    const float* W; const float* bias; float* C; int N; int bn;
    if (bx < 28)      { W = Wq; bias = bq; C = Qo; N = HID; bn = bx * 128; }
    else if (bx < 32) { W = Wk; bias = bk; C = Ko; N = NKV * HD; bn = (bx - 28) * 128; }
    else              { W = Wv; bias = bv; C = Vo; N = NKV * HD; bn = (bx - 32) * 128; }
    gemm_tf32<3>(X, W, bias, C, N, HID, blockIdx.y * 128, bn);
}

// O-projection (single tf32)
__global__ __launch_bounds__(256, 2) void out_gemm_kernel(
    const float* __restrict__ A, const float* __restrict__ Wo,
    float* __restrict__ C) {
    gemm_tf32<1>(A, Wo, nullptr, C, HID, HID, blockIdx.y * 128, blockIdx.x * 128);
}

// ---------------------------------------------------------------------------
// Copy cached prefix into full KV buffers
// ---------------------------------------------------------------------------
__global__ void copy_cache_kernel(const float* __restrict__ kc,
                                  const float* __restrict__ vc,
                                  float* __restrict__ Kf,
                                  float* __restrict__ Vf) {
    const int per_h = PAST * HD / 4;
    int i = blockIdx.x * blockDim.x + threadIdx.x;
    if (i >= NKV * per_h) return;
    int kh = i / per_h;
    int r = i - kh * per_h;
    const float4* ks = (const float4*)kc;
    const float4* vs = (const float4*)vc;
    float4* kd = (float4*)(Kf + (size_t)kh * KVLEN * HD);
    float4* vd = (float4*)(Vf + (size_t)kh * KVLEN * HD);
    kd[r] = ks[i];
    vd[r] = vs[i];
}

// ---------------------------------------------------------------------------
// RoPE + scatter. Q gets 1/sqrt(128) folded in. One block per token m.
// ---------------------------------------------------------------------------
__global__ void rope_kernel(const float* __restrict__ Qp,
                            const float* __restrict__ Kp,
                            const float* __restrict__ Vp,
                            const int* __restrict__ pos,
                            float* __restrict__ Qh,
                            float* __restrict__ Kf,
                            float* __restrict__ Vf) {
    const int m = blockIdx.x;
    const float p = (float)pos[m];
    const float qscale = 0.08838834764831845f;  // 1/sqrt(128)

    for (int idx = threadIdx.x; idx < NH * 64; idx += blockDim.x) {
        int h = idx >> 6;
        int d = idx & 63;
        float invf = (float)exp(-(double)d * (1.3815510557964274e+01 / 64.0));
        float ang = p * invf;
        float s, c;
        sincosf(ang, &s, &c);
        float x1 = Qp[(size_t)m * HID + h * HD + d];
        float x2 = Qp[(size_t)m * HID + h * HD + d + 64];
        float o1 = (x1 * c - x2 * s) * qscale;
        float o2 = (x2 * c + x1 * s) * qscale;
        float* dst = Qh + ((size_t)h * QLEN + m) * HD;
        dst[d] = o1;
        dst[d + 64] = o2;
    }
    for (int idx = threadIdx.x; idx < NKV * 64; idx += blockDim.x) {
        int kh = idx >> 6;
        int d = idx & 63;
        float invf = (float)exp(-(double)d * (1.3815510557964274e+01 / 64.0));
        float ang = p * invf;
        float s, c;
        sincosf(ang, &s, &c);
        float x1 = Kp[(size_t)m * (NKV * HD) + kh * HD + d];
        float x2 = Kp[(size_t)m * (NKV * HD) + kh * HD + d + 64];
        float* kd = Kf + ((size_t)kh * KVLEN + PAST + m) * HD;
        kd[d] = x1 * c - x2 * s;
        kd[d + 64] = x2 * c + x1 * s;
        float* vd = Vf + ((size_t)kh * KVLEN + PAST + m) * HD;
        vd[d] = Vp[(size_t)m * (NKV * HD) + kh * HD + d];
        vd[d + 64] = Vp[(size_t)m * (NKV * HD) + kh * HD + d + 64];
    }
}

// ---------------------------------------------------------------------------
// Flash attention, tf32 tensor-core. BQ=128, BKV=64, 256 threads (8 warps,
// each warp owns 16 q-rows). S=QK^T uses tf32x3, P.V single tf32.
// K is pre-split (hi/lo tf32) and V pre-converted to tf32 AT SMEM STORE TIME,
// so the MMA mainloop is pure bit-loads + HMMA (no per-use cvt/split).
// grid: (8 q-tiles, 28 heads), q-tiles issued longest-first. smem = 212.8 KB.
// ---------------------------------------------------------------------------
#define QS_STR 132
#define KS_STR 132
#define VS_STR 136
#define PS_STR 68
#define QS_FLOATS (128 * QS_STR)
#define KS_FLOATS (64 * KS_STR)
#define VS_FLOATS (64 * VS_STR)
#define PS_FLOATS (128 * PS_STR)
#define ATTN_SMEM_BYTES ((QS_FLOATS + 2 * KS_FLOATS + VS_FLOATS + PS_FLOATS) * 4)

__global__ __launch_bounds__(256, 1) void attn_kernel(
    const float* __restrict__ Qh, const float* __restrict__ Kf,
    const float* __restrict__ Vf, float* __restrict__ Aout) {
    extern __shared__ float sm[];
    float* QS = sm;                    // fp32 Q tile
    float* KH = QS + QS_FLOATS;        // tf32-hi bits of K
    float* KL = KH + KS_FLOATS;        // tf32-lo bits of K
    float* VT = KL + KS_FLOATS;        // tf32 bits of V
    float* PS = VT + VS_FLOATS;        // tf32 bits of P

    const int tid = threadIdx.x;
    const int lane = tid & 31;
    const int w = tid >> 5;       // 8 warps
    const int g = lane >> 2;      // 0..7
    const int c = lane & 3;       // 0..3
    const int h = blockIdx.y;
    const int qi = (int)gridDim.x - 1 - (int)blockIdx.x;  // longest blocks first
    const int m0 = qi * 128;
    const int kvh = h / NREP;

    // ---- prologue: load Q tile [128][128] into QS (fp32, persists)
    {
        const float4* qb = (const float4*)(Qh + ((size_t)h * QLEN + m0) * HD);
#pragma unroll
        for (int i = 0; i < 16; i++) {
            int idx = tid + i * 256;
            int r = idx >> 5, c4 = idx & 31;
            *(float4*)&QS[r * QS_STR + c4 * 4] = qb[idx];
        }
    }
    __syncthreads();

    const int ntiles = 48 + 2 * qi + 2;

    // per-row online softmax state (replicated across the 4 lanes of a group)
    float mrow[2] = {-1e30f, -1e30f};
    float lrow[2] = {0.f, 0.f};
    float o[16][4];
#pragma unroll
    for (int dt = 0; dt < 16; dt++)
#pragma unroll
        for (int j = 0; j < 4; j++) o[dt][j] = 0.f;

    // register prefetch of tile 0
    float4 kq[8], vq[8];
    {
        const float4* kb = (const float4*)(Kf + ((size_t)kvh * KVLEN) * HD);
        const float4* vb = (const float4*)(Vf + ((size_t)kvh * KVLEN) * HD);
#pragma unroll
        for (int i = 0; i < 8; i++) { kq[i] = kb[tid + i * 256]; vq[i] = vb[tid + i * 256]; }
    }

    for (int t = 0; t < ntiles; t++) {
        __syncthreads();   // all readers of previous K/V tile done
        // ---- store prefetched tile to smem, splitting K -> (hi,lo) tf32 and
        //      converting V -> tf32 ONCE per value (removes per-use ALU work)
#pragma unroll
        for (int i = 0; i < 8; i++) {
            int idx = tid + i * 256;
            int r = idx >> 5, c4 = (idx & 31) * 4;
            unsigned h0, l0, h1, l1, h2, l2, h3, l3;
            splitf(kq[i].x, h0, l0);
            splitf(kq[i].y, h1, l1);
            splitf(kq[i].z, h2, l2);
            splitf(kq[i].w, h3, l3);
            *(float4*)&KH[r * KS_STR + c4] = make_float4(
                __uint_as_float(h0), __uint_as_float(h1),
                __uint_as_float(h2), __uint_as_float(h3));
            *(float4*)&KL[r * KS_STR + c4] = make_float4(
                __uint_as_float(l0), __uint_as_float(l1),
                __uint_as_float(l2), __uint_as_float(l3));
            *(float4*)&VT[r * VS_STR + c4] = make_float4(
                __uint_as_float(f2tf32(vq[i].x)), __uint_as_float(f2tf32(vq[i].y)),
                __uint_as_float(f2tf32(vq[i].z)), __uint_as_float(f2tf32(vq[i].w)));
        }
        __syncthreads();
        // issue prefetch of next tile (hidden under the MMA work below)
        if (t + 1 < ntiles) {
            const float4* kb = (const float4*)(Kf + ((size_t)kvh * KVLEN + (t + 1) * 64) * HD);
            const float4* vb = (const float4*)(Vf + ((size_t)kvh * KVLEN + (t + 1) * 64) * HD);
#pragma unroll
            for (int i = 0; i < 8; i++) { kq[i] = kb[tid + i * 256]; vq[i] = vb[tid + i * 256]; }
        }

        // ---- S = Q K^T (tf32x3), per warp: 16 x 64
        float s[8][4];
#pragma unroll
        for (int nt = 0; nt < 8; nt++)
#pragma unroll
            for (int j = 0; j < 4; j++) s[nt][j] = 0.f;

        const float* QSw = QS + (w * 16) * QS_STR;
#pragma unroll 2
        for (int kt = 0; kt < 16; kt++) {
            unsigned ah[4], al[4];
            splitf(QSw[g * QS_STR + kt * 8 + c],            ah[0], al[0]);
            splitf(QSw[(g + 8) * QS_STR + kt * 8 + c],      ah[1], al[1]);
            splitf(QSw[g * QS_STR + kt * 8 + c + 4],        ah[2], al[2]);
            splitf(QSw[(g + 8) * QS_STR + kt * 8 + c + 4],  ah[3], al[3]);
#pragma unroll
            for (int nt = 0; nt < 8; nt++) {
                unsigned bh[2], bl[2];
                bh[0] = __float_as_uint(KH[(nt * 8 + g) * KS_STR + kt * 8 + c]);
                bh[1] = __float_as_uint(KH[(nt * 8 + g) * KS_STR + kt * 8 + c + 4]);
                bl[0] = __float_as_uint(KL[(nt * 8 + g) * KS_STR + kt * 8 + c]);
                bl[1] = __float_as_uint(KL[(nt * 8 + g) * KS_STR + kt * 8 + c + 4]);
                mma8(s[nt], ah, bh);
                mma8(s[nt], al, bh);
                mma8(s[nt], ah, bl);
            }
        }

        // ---- causal mask (only last two tiles touch the diagonal)
        if (t >= ntiles - 2) {
            int base_col = t * 64;
            int lim0 = PAST + m0 + w * 16 + g;
            int lim1 = lim0 + 8;
#pragma unroll
            for (int nt = 0; nt < 8; nt++) {
                int c0 = base_col + nt * 8 + 2 * c;
                if (c0 > lim0)     s[nt][0] = -1e30f;
                if (c0 + 1 > lim0) s[nt][1] = -1e30f;
                if (c0 > lim1)     s[nt][2] = -1e30f;
                if (c0 + 1 > lim1) s[nt][3] = -1e30f;
            }
        }

        // ---- online softmax (rows g and g+8; reductions over the 4-lane group)
#pragma unroll
        for (int rr = 0; rr < 2; rr++) {
            float mx = -1e30f;
#pragma unroll
            for (int nt = 0; nt < 8; nt++)
                mx = fmaxf(mx, fmaxf(s[nt][2 * rr], s[nt][2 * rr + 1]));
            mx = fmaxf(mx, __shfl_xor_sync(0xffffffffu, mx, 1));
            mx = fmaxf(mx, __shfl_xor_sync(0xffffffffu, mx, 2));
            float mn = fmaxf(mrow[rr], mx);
            float alpha = __expf(mrow[rr] - mn);
            mrow[rr] = mn;
            float ls = 0.f;
#pragma unroll
            for (int nt = 0; nt < 8; nt++) {
                float e0 = __expf(s[nt][2 * rr] - mn);
                float e1 = __expf(s[nt][2 * rr + 1] - mn);
                s[nt][2 * rr] = e0;
                s[nt][2 * rr + 1] = e1;
                ls += e0 + e1;
            }
            ls += __shfl_xor_sync(0xffffffffu, ls, 1);
            ls += __shfl_xor_sync(0xffffffffu, ls, 2);
            lrow[rr] = lrow[rr] * alpha + ls;
#pragma unroll
            for (int dt = 0; dt < 16; dt++) {
                o[dt][2 * rr] *= alpha;
                o[dt][2 * rr + 1] *= alpha;
            }
        }

        // ---- store P to smem as tf32 bit-patterns (A-frag layout friendly)
        {
            float* p0 = PS + (w * 16 + g) * PS_STR;
            float* p1 = PS + (w * 16 + g + 8) * PS_STR;
#pragma unroll
            for (int nt = 0; nt < 8; nt++) {
                *(float2*)&p0[nt * 8 + 2 * c] = make_float2(
                    __uint_as_float(f2tf32(s[nt][0])), __uint_as_float(f2tf32(s[nt][1])));
                *(float2*)&p1[nt * 8 + 2 * c] = make_float2(
                    __uint_as_float(f2tf32(s[nt][2])), __uint_as_float(f2tf32(s[nt][3])));
            }
        }
        __syncwarp();

        // ---- O += P @ V (single tf32), per warp: 16 x 128
        const float* PSw = PS + (w * 16) * PS_STR;
#pragma unroll
        for (int ktv = 0; ktv < 8; ktv++) {
            unsigned a[4];
            a[0] = __float_as_uint(PSw[g * PS_STR + ktv * 8 + c]);
            a[1] = __float_as_uint(PSw[(g + 8) * PS_STR + ktv * 8 + c]);
            a[2] = __float_as_uint(PSw[g * PS_STR + ktv * 8 + c + 4]);
            a[3] = __float_as_uint(PSw[(g + 8) * PS_STR + ktv * 8 + c + 4]);
#pragma unroll
            for (int dt = 0; dt < 16; dt++) {
                unsigned b[2];
                b[0] = __float_as_uint(VT[(ktv * 8 + c) * VS_STR + dt * 8 + g]);
                b[1] = __float_as_uint(VT[(ktv * 8 + c + 4) * VS_STR + dt * 8 + g]);
                mma8(o[dt], a, b);
            }
        }
    }

    // ---- normalize and write [1024][3584]
#pragma unroll
    for (int rr = 0; rr < 2; rr++) {
        float inv = 1.0f / lrow[rr];
        int row = m0 + w * 16 + g + rr * 8;
        float* dst = Aout + (size_t)row * HID + h * HD;
#pragma unroll
        for (int dt = 0; dt < 16; dt++) {
            *(float2*)&dst[dt * 8 + 2 * c] =
                make_float2(o[dt][2 * rr] * inv, o[dt][2 * rr + 1] * inv);
        }
    }
}

// ---------------------------------------------------------------------------
// Launch
// ---------------------------------------------------------------------------
extern "C" void kernel_launch(void* const* d_in, const int* in_sizes, int n_in,
                              void* d_out, int out_size) {
    (void)in_sizes; (void)n_in; (void)out_size;
    const float* X  = (const float*)d_in[0];
    const float* kc = (const float*)d_in[1];
    const float* vc = (const float*)d_in[2];
    const float* Wq = (const float*)d_in[3];
    const float* bq = (const float*)d_in[4];
    const float* Wk = (const float*)d_in[5];
    const float* bk = (const float*)d_in[6];
    const float* Wv = (const float*)d_in[7];
    const float* bv = (const float*)d_in[8];
    const float* Wo = (const float*)d_in[9];
    const int*  pos = (const int*)d_in[10];
    float* out = (float*)d_out;

    float *qp, *kp, *vp, *qh, *kf, *vf, *attn;
    cudaGetSymbolAddress((void**)&qp, g_qp);
    cudaGetSymbolAddress((void**)&kp, g_kp);
    cudaGetSymbolAddress((void**)&vp, g_vp);
    cudaGetSymbolAddress((void**)&qh, g_qh);
    cudaGetSymbolAddress((void**)&kf, g_kf);
    cudaGetSymbolAddress((void**)&vf, g_vf);
    cudaGetSymbolAddress((void**)&attn, g_attn);

    static bool attr_set = false;
    if (!attr_set) {
        cudaFuncSetAttribute(qkv_gemm_kernel,
                             cudaFuncAttributeMaxDynamicSharedMemorySize, GEMM_SMEM_BYTES);
        cudaFuncSetAttribute(out_gemm_kernel,
                             cudaFuncAttributeMaxDynamicSharedMemorySize, GEMM_SMEM_BYTES);
        cudaFuncSetAttribute(attn_kernel,
                             cudaFuncAttributeMaxDynamicSharedMemorySize, ATTN_SMEM_BYTES);
        attr_set = true;
    }

    // 1) fused QKV projection (tf32x3 tensor-core)
    qkv_gemm_kernel<<<dim3(36, 8), 256, GEMM_SMEM_BYTES>>>(
        X, Wq, bq, Wk, bk, Wv, bv, qp, kp, vp);

    // 2) KV cache prefix copy
    {
        int total = NKV * PAST * HD / 4;
        copy_cache_kernel<<<(total + 255) / 256, 256>>>(kc, vc, kf, vf);
    }

    // 3) RoPE + scatter into head-major / full-KV layouts
    rope_kernel<<<QLEN, 256>>>(qp, kp, vp, pos, qh, kf, vf);

    // 4) flash attention (tensor-core, pre-split K / pre-cvt V)
    attn_kernel<<<dim3(8, NH), 256, ATTN_SMEM_BYTES>>>(qh, kf, vf, attn);

    // 5) output projection (single tf32)
    out_gemm_kernel<<<dim3(28, 8), 256, GEMM_SMEM_BYTES>>>(attn, Wo, out);
}

// round 12
// speedup vs baseline: 2.2609x; 1.1176x over previous
#include <cuda_runtime.h>
#include <cuda_bf16.h>
#include <math.h>
#include <stdint.h>

// ---------------------------------------------------------------------------
// Problem constants
// ---------------------------------------------------------------------------
#define QLEN 1024
#define HID 3584
#define NH 28
#define NKV 4
#define HD 128
#define PAST 3072
#define KVLEN 4096          // PAST + QLEN
#define NREP 7              // NH / NKV

// ---------------------------------------------------------------------------
// Scratch (no allocations allowed -> __device__ globals)
// NOTE: deliberately identical footprint to the last PASSING run (R7) plus
// nothing — the 51MB g_wo global added in R8 is suspected in the container
// failures and has been removed.
// ---------------------------------------------------------------------------
__device__ float g_qp[QLEN * HID];          // raw Q proj  [1024][3584]
__device__ float g_kp[QLEN * NKV * HD];     // raw K proj  [1024][512]
__device__ float g_vp[QLEN * NKV * HD];     // raw V proj  [1024][512]
__device__ float g_qh[NH * QLEN * HD];      // roped Q (scaled), head-major [28][1024][128]
__device__ float g_kf[NKV * KVLEN * HD];    // full K [4][4096][128]
__device__ float g_vf[NKV * KVLEN * HD];    // full V [4][4096][128]
__device__ float g_attn[QLEN * HID];        // attention out, tf32-rounded bits

// ---------------------------------------------------------------------------
// PTX helpers
// ---------------------------------------------------------------------------
__device__ __forceinline__ unsigned f2tf32(float x) {
    unsigned r;
    asm("cvt.rna.tf32.f32 %0, %1;" : "=r"(r) : "f"(x));
    return r;
}
__device__ __forceinline__ void splitf(float x, unsigned& hi, unsigned& lo) {
    hi = f2tf32(x);
    lo = f2tf32(x - __uint_as_float(hi));
}
__device__ __forceinline__ void mma8(float* d, const unsigned* a, const unsigned* b) {
    asm volatile(
        "mma.sync.aligned.m16n8k8.row.col.f32.tf32.tf32.f32 "
        "{%0,%1,%2,%3}, {%4,%5,%6,%7}, {%8,%9}, {%0,%1,%2,%3};\n"
        : "+f"(d[0]), "+f"(d[1]), "+f"(d[2]), "+f"(d[3])
        : "r"(a[0]), "r"(a[1]), "r"(a[2]), "r"(a[3]), "r"(b[0]), "r"(b[1]));
}
__device__ __forceinline__ void cp16(const float* smem_dst, const float* gmem_src) {
    unsigned s = (unsigned)__cvta_generic_to_shared(smem_dst);
    asm volatile("cp.async.cg.shared.global [%0], [%1], 16;\n"
                 :: "r"(s), "l"(__cvta_generic_to_global(gmem_src)));
}
#define CP_COMMIT() asm volatile("cp.async.commit_group;\n")
#define CP_WAIT0()  asm volatile("cp.async.wait_group 0;\n")

// ---------------------------------------------------------------------------
// tf32 GEMM: 128x128 tile, BK=32, 256 threads (8 warps, 4x2), double-buffered
// cp.async.
//   SPLIT=3 -> tf32x3 (near-fp32; per-use split)
//   SPLIT=1 -> single tf32; if APRE/BPRE the operand is already tf32-rounded
//              bits in gmem, so that side needs no conversion in the mainloop.
// A: MxK row-major, B: KxN row-major, C row-major.
// ---------------------------------------------------------------------------
#define AS_STR 36
#define BS_STR 136
#define AS_BUF (128 * AS_STR)
#define BS_BUF (32 * BS_STR)
#define GEMM_SMEM_BYTES ((2 * AS_BUF + 2 * BS_BUF) * 4)

template <int SPLIT, bool APRE, bool BPRE>
__device__ __forceinline__ void gemm_tf32(const float* __restrict__ A,
                                          const float* __restrict__ B,
                                          const float* __restrict__ bias,
                                          float* __restrict__ C,
                                          int N, int K, int bm, int bn) {
    extern __shared__ float sm[];
    float* AS = sm;
    float* BS = sm + 2 * AS_BUF;

    const int tid = threadIdx.x;
    const int lane = tid & 31;
    const int wid = tid >> 5;
    const int wm = (wid >> 1) * 32;
    const int wn = (wid & 1) * 64;
    const int g = lane >> 2;
    const int c = lane & 3;

    float acc[2][8][4];
#pragma unroll
    for (int mt = 0; mt < 2; mt++)
#pragma unroll
        for (int nt = 0; nt < 8; nt++)
#pragma unroll
            for (int j = 0; j < 4; j++) acc[mt][nt][j] = 0.f;

    const int nk = K / 32;

    // prefetch tile 0
    {
        float* as = AS;
        float* bs = BS;
#pragma unroll
        for (int i = 0; i < 4; i++) {
            int idx = tid + i * 256;
            int r = idx >> 3, cc = (idx & 7) * 4;
            cp16(&as[r * AS_STR + cc], &A[(size_t)(bm + r) * K + cc]);
        }
#pragma unroll
        for (int i = 0; i < 4; i++) {
            int idx = tid + i * 256;
            int r = idx >> 5, cc = (idx & 31) * 4;
            cp16(&bs[r * BS_STR + cc], &B[(size_t)r * N + bn + cc]);
        }
        CP_COMMIT();
    }

    for (int it = 0; it < nk; it++) {
        CP_WAIT0();
        __syncthreads();
        if (it + 1 < nk) {
            int k0 = (it + 1) * 32;
            float* as = AS + ((it + 1) & 1) * AS_BUF;
            float* bs = BS + ((it + 1) & 1) * BS_BUF;
#pragma unroll
            for (int i = 0; i < 4; i++) {
                int idx = tid + i * 256;
                int r = idx >> 3, cc = (idx & 7) * 4;
                cp16(&as[r * AS_STR + cc], &A[(size_t)(bm + r) * K + k0 + cc]);
            }
#pragma unroll
            for (int i = 0; i < 4; i++) {
                int idx = tid + i * 256;
                int r = idx >> 5, cc = (idx & 31) * 4;
                cp16(&bs[r * BS_STR + cc], &B[(size_t)(k0 + r) * N + bn + cc]);
            }
            CP_COMMIT();
        }
        const float* as = AS + (it & 1) * AS_BUF;
        const float* bs = BS + (it & 1) * BS_BUF;

#pragma unroll
        for (int kt = 0; kt < 4; kt++) {
            unsigned ah[2][4], al[2][4];
#pragma unroll
            for (int mt = 0; mt < 2; mt++) {
                int rb = wm + mt * 16;
                float f0 = as[(rb + g) * AS_STR + kt * 8 + c];
                float f1 = as[(rb + g + 8) * AS_STR + kt * 8 + c];
                float f2 = as[(rb + g) * AS_STR + kt * 8 + c + 4];
                float f3 = as[(rb + g + 8) * AS_STR + kt * 8 + c + 4];
                if (SPLIT == 3) {
                    splitf(f0, ah[mt][0], al[mt][0]);
                    splitf(f1, ah[mt][1], al[mt][1]);
                    splitf(f2, ah[mt][2], al[mt][2]);
                    splitf(f3, ah[mt][3], al[mt][3]);
                } else if (APRE) {
                    ah[mt][0] = __float_as_uint(f0); ah[mt][1] = __float_as_uint(f1);
                    ah[mt][2] = __float_as_uint(f2); ah[mt][3] = __float_as_uint(f3);
                } else {
                    ah[mt][0] = f2tf32(f0); ah[mt][1] = f2tf32(f1);
                    ah[mt][2] = f2tf32(f2); ah[mt][3] = f2tf32(f3);
                }
            }
#pragma unroll
            for (int nt = 0; nt < 8; nt++) {
                float f0 = bs[(kt * 8 + c) * BS_STR + wn + nt * 8 + g];
                float f1 = bs[(kt * 8 + c + 4) * BS_STR + wn + nt * 8 + g];
                unsigned bh[2], bl[2];
                if (SPLIT == 3) {
                    splitf(f0, bh[0], bl[0]);
                    splitf(f1, bh[1], bl[1]);
                } else if (BPRE) {
                    bh[0] = __float_as_uint(f0); bh[1] = __float_as_uint(f1);
                } else {
                    bh[0] = f2tf32(f0); bh[1] = f2tf32(f1);
                }
#pragma unroll
                for (int mt = 0; mt < 2; mt++) {
                    mma8(acc[mt][nt], ah[mt], bh);
                    if (SPLIT == 3) {
                        mma8(acc[mt][nt], al[mt], bh);
                        mma8(acc[mt][nt], ah[mt], bl);
                    }
                }
            }
        }
    }

    // epilogue
#pragma unroll
    for (int mt = 0; mt < 2; mt++) {
        int r0 = bm + wm + mt * 16 + g;
#pragma unroll
        for (int nt = 0; nt < 8; nt++) {
            int c0 = bn + wn + nt * 8 + 2 * c;
            float2 v0 = make_float2(acc[mt][nt][0], acc[mt][nt][1]);
            float2 v1 = make_float2(acc[mt][nt][2], acc[mt][nt][3]);
            if (bias) {
                float b0 = bias[c0], b1 = bias[c0 + 1];
                v0.x += b0; v0.y += b1;
                v1.x += b0; v1.y += b1;
            }
            *(float2*)&C[(size_t)r0 * N + c0] = v0;
            *(float2*)&C[(size_t)(r0 + 8) * N + c0] = v1;
        }
    }
}

// Fused QKV projection: bx<28 -> Q (x3), [28,32) -> K (x3), [32,36) -> V (x1:
// V gets truncated to single tf32 in the attention kernel anyway, so x3
// precision on the V projection is wasted).
__global__ __launch_bounds__(256, 2) void qkv_gemm_kernel(
    const float* __restrict__ X,
    const float* __restrict__ Wq, const float* __restrict__ bq,
    const float* __restrict__ Wk, const float* __restrict__ bk,
    const float* __restrict__ Wv, const float* __restrict__ bv,
    float* __restrict__ Qo, float* __restrict__ Ko, float* __restrict__ Vo) {
    int bx = blockIdx.x;
    if (bx < 28) {
        gemm_tf32<3, false, false>(X, Wq, bq, Qo, HID, HID, blockIdx.y * 128, bx * 128);
    } else if (bx < 32) {
        gemm_tf32<3, false, false>(X, Wk, bk, Ko, NKV * HD, HID, blockIdx.y * 128, (bx - 28) * 128);
    } else {
        gemm_tf32<1, false, false>(X, Wv, bv, Vo, NKV * HD, HID, blockIdx.y * 128, (bx - 32) * 128);
    }
}

// O-projection: A (g_attn) is tf32-pre-rounded by the attention epilogue
// (APRE, no extra buffer needed); Wo converted per-use as in the last
// passing kernel.
__global__ __launch_bounds__(256, 2) void out_gemm_kernel(
    const float* __restrict__ A, const float* __restrict__ Wo,
    float* __restrict__ C) {
    gemm_tf32<1, true, false>(A, Wo, nullptr, C, HID, HID, blockIdx.y * 128, blockIdx.x * 128);
}

// ---------------------------------------------------------------------------
// Copy cached prefix into full KV buffers
// ---------------------------------------------------------------------------
__global__ void copy_cache_kernel(const float* __restrict__ kc,
                                  const float* __restrict__ vc,
                                  float* __restrict__ Kf,
                                  float* __restrict__ Vf) {
    const int per_h = PAST * HD / 4;
    int i = blockIdx.x * blockDim.x + threadIdx.x;
    if (i >= NKV * per_h) return;
    int kh = i / per_h;
    int r = i - kh * per_h;
    const float4* ks = (const float4*)kc;
    const float4* vs = (const float4*)vc;
    float4* kd = (float4*)(Kf + (size_t)kh * KVLEN * HD);
    float4* vd = (float4*)(Vf + (size_t)kh * KVLEN * HD);
    kd[r] = ks[i];
    vd[r] = vs[i];
}

// ---------------------------------------------------------------------------
// RoPE + scatter. Q gets 1/sqrt(128) folded in. One block per token m.
// ---------------------------------------------------------------------------
__global__ void rope_kernel(const float* __restrict__ Qp,
                            const float* __restrict__ Kp,
                            const float* __restrict__ Vp,
                            const int* __restrict__ pos,
                            float* __restrict__ Qh,
                            float* __restrict__ Kf,
                            float* __restrict__ Vf) {
    const int m = blockIdx.x;
    const float p = (float)pos[m];
    const float qscale = 0.08838834764831845f;  // 1/sqrt(128)

    for (int idx = threadIdx.x; idx < NH * 64; idx += blockDim.x) {
        int h = idx >> 6;
        int d = idx & 63;
        float invf = (float)exp(-(double)d * (1.3815510557964274e+01 / 64.0));
        float ang = p * invf;
        float s, c;
        sincosf(ang, &s, &c);
        float x1 = Qp[(size_t)m * HID + h * HD + d];
        float x2 = Qp[(size_t)m * HID + h * HD + d + 64];
        float o1 = (x1 * c - x2 * s) * qscale;
        float o2 = (x2 * c + x1 * s) * qscale;
        float* dst = Qh + ((size_t)h * QLEN + m) * HD;
        dst[d] = o1;
        dst[d + 64] = o2;
    }
    for (int idx = threadIdx.x; idx < NKV * 64; idx += blockDim.x) {
        int kh = idx >> 6;
        int d = idx & 63;
        float invf = (float)exp(-(double)d * (1.3815510557964274e+01 / 64.0));
        float ang = p * invf;
        float s, c;
        sincosf(ang, &s, &c);
        float x1 = Kp[(size_t)m * (NKV * HD) + kh * HD + d];
        float x2 = Kp[(size_t)m * (NKV * HD) + kh * HD + d + 64];
        float* kd = Kf + ((size_t)kh * KVLEN + PAST + m) * HD;
        kd[d] = x1 * c - x2 * s;
        kd[d + 64] = x2 * c + x1 * s;
        float* vd = Vf + ((size_t)kh * KVLEN + PAST + m) * HD;
        vd[d] = Vp[(size_t)m * (NKV * HD) + kh * HD + d];
        vd[d + 64] = Vp[(size_t)m * (NKV * HD) + kh * HD + d + 64];
    }
}

// ---------------------------------------------------------------------------
// Flash attention, tf32 tensor-core. BQ=128, BKV=64, 256 threads (8 warps,
// each warp owns 16 q-rows). S=QK^T uses tf32x2 (Q split hi/lo, K single),
// P.V single tf32. K and V converted to tf32 ONCE at smem store. Epilogue
// writes tf32-rounded output so the O-projection's A side needs no cvt.
// grid: (8 q-tiles, 28 heads), longest-first. smem = 171 KB.
// ---------------------------------------------------------------------------
#define QS_STR 132
#define KS_STR 132
#define VS_STR 136
#define PS_STR 68
#define QS_FLOATS (128 * QS_STR)
#define KS_FLOATS (64 * KS_STR)
#define VS_FLOATS (64 * VS_STR)
#define PS_FLOATS (128 * PS_STR)
#define ATTN_SMEM_BYTES ((QS_FLOATS + KS_FLOATS + VS_FLOATS + PS_FLOATS) * 4)

__global__ __launch_bounds__(256, 1) void attn_kernel(
    const float* __restrict__ Qh, const float* __restrict__ Kf,
    const float* __restrict__ Vf, float* __restrict__ Aout) {
    extern __shared__ float sm[];
    float* QS = sm;                    // fp32 Q tile
    float* KH = QS + QS_FLOATS;        // tf32 bits of K (single)
    float* VT = KH + KS_FLOATS;        // tf32 bits of V
    float* PS = VT + VS_FLOATS;        // tf32 bits of P

    const int tid = threadIdx.x;
    const int lane = tid & 31;
    const int w = tid >> 5;       // 8 warps
    const int g = lane >> 2;      // 0..7
    const int c = lane & 3;       // 0..3
    const int h = blockIdx.y;
    const int qi = (int)gridDim.x - 1 - (int)blockIdx.x;  // longest blocks first
    const int m0 = qi * 128;
    const int kvh = h / NREP;

    // ---- prologue: load Q tile [128][128] into QS (fp32, persists)
    {
        const float4* qb = (const float4*)(Qh + ((size_t)h * QLEN + m0) * HD);
#pragma unroll
        for (int i = 0; i < 16; i++) {
            int idx = tid + i * 256;
            int r = idx >> 5, c4 = idx & 31;
            *(float4*)&QS[r * QS_STR + c4 * 4] = qb[idx];
        }
    }
    __syncthreads();

    const int ntiles = 48 + 2 * qi + 2;

    float mrow[2] = {-1e30f, -1e30f};
    float lrow[2] = {0.f, 0.f};
    float o[16][4];
#pragma unroll
    for (int dt = 0; dt < 16; dt++)
#pragma unroll
        for (int j = 0; j < 4; j++) o[dt][j] = 0.f;

    // register prefetch of tile 0
    float4 kq[8], vq[8];
    {
        const float4* kb = (const float4*)(Kf + ((size_t)kvh * KVLEN) * HD);
        const float4* vb = (const float4*)(Vf + ((size_t)kvh * KVLEN) * HD);
#pragma unroll
        for (int i = 0; i < 8; i++) { kq[i] = kb[tid + i * 256]; vq[i] = vb[tid + i * 256]; }
    }

    for (int t = 0; t < ntiles; t++) {
        __syncthreads();   // all readers of previous K/V tile done
        // ---- store prefetched tile to smem, converting K and V to tf32 once
#pragma unroll
        for (int i = 0; i < 8; i++) {
            int idx = tid + i * 256;
            int r = idx >> 5, c4 = (idx & 31) * 4;
            *(float4*)&KH[r * KS_STR + c4] = make_float4(
                __uint_as_float(f2tf32(kq[i].x)), __uint_as_float(f2tf32(kq[i].y)),
                __uint_as_float(f2tf32(kq[i].z)), __uint_as_float(f2tf32(kq[i].w)));
            *(float4*)&VT[r * VS_STR + c4] = make_float4(
                __uint_as_float(f2tf32(vq[i].x)), __uint_as_float(f2tf32(vq[i].y)),
                __uint_as_float(f2tf32(vq[i].z)), __uint_as_float(f2tf32(vq[i].w)));
        }
        __syncthreads();
        // prefetch next tile (hidden under MMA work)
        if (t + 1 < ntiles) {
            const float4* kb = (const float4*)(Kf + ((size_t)kvh * KVLEN + (t + 1) * 64) * HD);
            const float4* vb = (const float4*)(Vf + ((size_t)kvh * KVLEN + (t + 1) * 64) * HD);
#pragma unroll
            for (int i = 0; i < 8; i++) { kq[i] = kb[tid + i * 256]; vq[i] = vb[tid + i * 256]; }
        }

        // ---- S = Q K^T (tf32x2: Q hi/lo, K single), per warp: 16 x 64
        float s[8][4];
#pragma unroll
        for (int nt = 0; nt < 8; nt++)
#pragma unroll
            for (int j = 0; j < 4; j++) s[nt][j] = 0.f;

        const float* QSw = QS + (w * 16) * QS_STR;
#pragma unroll 2
        for (int kt = 0; kt < 16; kt++) {
            unsigned ah[4], al[4];
            splitf(QSw[g * QS_STR + kt * 8 + c],            ah[0], al[0]);
            splitf(QSw[(g + 8) * QS_STR + kt * 8 + c],      ah[1], al[1]);
            splitf(QSw[g * QS_STR + kt * 8 + c + 4],        ah[2], al[2]);
            splitf(QSw[(g + 8) * QS_STR + kt * 8 + c + 4],  ah[3], al[3]);
#pragma unroll
            for (int nt = 0; nt < 8; nt++) {
                unsigned bh[2];
                bh[0] = __float_as_uint(KH[(nt * 8 + g) * KS_STR + kt * 8 + c]);
                bh[1] = __float_as_uint(KH[(nt * 8 + g) * KS_STR + kt * 8 + c + 4]);
                mma8(s[nt], ah, bh);
                mma8(s[nt], al, bh);
            }
        }

        // ---- causal mask (only last two tiles touch the diagonal)
        if (t >= ntiles - 2) {
            int base_col = t * 64;
            int lim0 = PAST + m0 + w * 16 + g;
            int lim1 = lim0 + 8;
#pragma unroll
            for (int nt = 0; nt < 8; nt++) {
                int c0 = base_col + nt * 8 + 2 * c;
                if (c0 > lim0)     s[nt][0] = -1e30f;
                if (c0 + 1 > lim0) s[nt][1] = -1e30f;
                if (c0 > lim1)     s[nt][2] = -1e30f;
                if (c0 + 1 > lim1) s[nt][3] = -1e30f;
            }
        }

        // ---- online softmax (rows g and g+8; reductions over the 4-lane group)
#pragma unroll
        for (int rr = 0; rr < 2; rr++) {
            float mx = -1e30f;
#pragma unroll
            for (int nt = 0; nt < 8; nt++)
                mx = fmaxf(mx, fmaxf(s[nt][2 * rr], s[nt][2 * rr + 1]));
            mx = fmaxf(mx, __shfl_xor_sync(0xffffffffu, mx, 1));
            mx = fmaxf(mx, __shfl_xor_sync(0xffffffffu, mx, 2));
            float mn = fmaxf(mrow[rr], mx);
            float alpha = __expf(mrow[rr] - mn);
            mrow[rr] = mn;
            float ls = 0.f;
#pragma unroll
            for (int nt = 0; nt < 8; nt++) {
                float e0 = __expf(s[nt][2 * rr] - mn);
                float e1 = __expf(s[nt][2 * rr + 1] - mn);
                s[nt][2 * rr] = e0;
                s[nt][2 * rr + 1] = e1;
                ls += e0 + e1;
            }
            ls += __shfl_xor_sync(0xffffffffu, ls, 1);
            ls += __shfl_xor_sync(0xffffffffu, ls, 2);
            lrow[rr] = lrow[rr] * alpha + ls;
#pragma unroll
            for (int dt = 0; dt < 16; dt++) {
                o[dt][2 * rr] *= alpha;
                o[dt][2 * rr + 1] *= alpha;
            }
        }

        // ---- store P to smem as tf32 bit-patterns
        {
            float* p0 = PS + (w * 16 + g) * PS_STR;
            float* p1 = PS + (w * 16 + g + 8) * PS_STR;
#pragma unroll
            for (int nt = 0; nt < 8; nt++) {
                *(float2*)&p0[nt * 8 + 2 * c] = make_float2(
                    __uint_as_float(f2tf32(s[nt][0])), __uint_as_float(f2tf32(s[nt][1])));
                *(float2*)&p1[nt * 8 + 2 * c] = make_float2(
                    __uint_as_float(f2tf32(s[nt][2])), __uint_as_float(f2tf32(s[nt][3])));
            }
        }
        __syncwarp();

        // ---- O += P @ V (single tf32), per warp: 16 x 128
        const float* PSw = PS + (w * 16) * PS_STR;
#pragma unroll
        for (int ktv = 0; ktv < 8; ktv++) {
            unsigned a[4];
            a[0] = __float_as_uint(PSw[g * PS_STR + ktv * 8 + c]);
            a[1] = __float_as_uint(PSw[(g + 8) * PS_STR + ktv * 8 + c]);
            a[2] = __float_as_uint(PSw[g * PS_STR + ktv * 8 + c + 4]);
            a[3] = __float_as_uint(PSw[(g + 8) * PS_STR + ktv * 8 + c + 4]);
#pragma unroll
            for (int dt = 0; dt < 16; dt++) {
                unsigned b[2];
                b[0] = __float_as_uint(VT[(ktv * 8 + c) * VS_STR + dt * 8 + g]);
                b[1] = __float_as_uint(VT[(ktv * 8 + c + 4) * VS_STR + dt * 8 + g]);
                mma8(o[dt], a, b);
            }
        }
    }

    // ---- normalize and write [1024][3584], pre-rounded to tf32 for O-proj
#pragma unroll
    for (int rr = 0; rr < 2; rr++) {
        float inv = 1.0f / lrow[rr];
        int row = m0 + w * 16 + g + rr * 8;
        float* dst = Aout + (size_t)row * HID + h * HD;
#pragma unroll
        for (int dt = 0; dt < 16; dt++) {
            *(float2*)&dst[dt * 8 + 2 * c] = make_float2(
                __uint_as_float(f2tf32(o[dt][2 * rr] * inv)),
                __uint_as_float(f2tf32(o[dt][2 * rr + 1] * inv)));
        }
    }
}

// ---------------------------------------------------------------------------
// Launch
// ---------------------------------------------------------------------------
extern "C" void kernel_launch(void* const* d_in, const int* in_sizes, int n_in,
                              void* d_out, int out_size) {
    (void)in_sizes; (void)n_in; (void)out_size;
    const float* X  = (const float*)d_in[0];
    const float* kc = (const float*)d_in[1];
    const float* vc = (const float*)d_in[2];
    const float* Wq = (const float*)d_in[3];
    const float* bq = (const float*)d_in[4];
    const float* Wk = (const float*)d_in[5];
    const float* bk = (const float*)d_in[6];
    const float* Wv = (const float*)d_in[7];
    const float* bv = (const float*)d_in[8];
    const float* Wo = (const float*)d_in[9];
    const int*  pos = (const int*)d_in[10];
    float* out = (float*)d_out;

    float *qp, *kp, *vp, *qh, *kf, *vf, *attn;
    cudaGetSymbolAddress((void**)&qp, g_qp);
    cudaGetSymbolAddress((void**)&kp, g_kp);
    cudaGetSymbolAddress((void**)&vp, g_vp);
    cudaGetSymbolAddress((void**)&qh, g_qh);
    cudaGetSymbolAddress((void**)&kf, g_kf);
    cudaGetSymbolAddress((void**)&vf, g_vf);
    cudaGetSymbolAddress((void**)&attn, g_attn);

    static bool attr_set = false;
    if (!attr_set) {
        cudaFuncSetAttribute(qkv_gemm_kernel,
                             cudaFuncAttributeMaxDynamicSharedMemorySize, GEMM_SMEM_BYTES);
        cudaFuncSetAttribute(out_gemm_kernel,
                             cudaFuncAttributeMaxDynamicSharedMemorySize, GEMM_SMEM_BYTES);
        cudaFuncSetAttribute(attn_kernel,
                             cudaFuncAttributeMaxDynamicSharedMemorySize, ATTN_SMEM_BYTES);
        attr_set = true;
    }

    // 1) fused QKV projection (Q,K: tf32x3; V: single tf32)
    qkv_gemm_kernel<<<dim3(36, 8), 256, GEMM_SMEM_BYTES>>>(
        X, Wq, bq, Wk, bk, Wv, bv, qp, kp, vp);

    // 2) KV cache prefix copy
    {
        int total = NKV * PAST * HD / 4;
        copy_cache_kernel<<<(total + 255) / 256, 256>>>(kc, vc, kf, vf);
    }

    // 3) RoPE + scatter into head-major / full-KV layouts
    rope_kernel<<<QLEN, 256>>>(qp, kp, vp, pos, qh, kf, vf);

    // 4) flash attention (tensor-core, tf32x2 logits)
    attn_kernel<<<dim3(8, NH), 256, ATTN_SMEM_BYTES>>>(qh, kf, vf, attn);

    // 5) output projection (A pre-rounded by attn epilogue; Wo cvt per-use)
    out_gemm_kernel<<<dim3(28, 8), 256, GEMM_SMEM_BYTES>>>(attn, Wo, out);
}

// round 15
// speedup vs baseline: 2.3947x; 1.0592x over previous
#include <cuda_runtime.h>
#include <cuda_bf16.h>
#include <math.h>
#include <stdint.h>

// ---------------------------------------------------------------------------
// Problem constants
// ---------------------------------------------------------------------------
#define QLEN 1024
#define HID 3584
#define NH 28
#define NKV 4
#define HD 128
#define PAST 3072
#define KVLEN 4096          // PAST + QLEN
#define NREP 7              // NH / NKV

// ---------------------------------------------------------------------------
// Scratch (no allocations allowed -> __device__ globals)
// ---------------------------------------------------------------------------
__device__ float g_qp[QLEN * HID];          // raw Q proj  [1024][3584]
__device__ float g_kp[QLEN * NKV * HD];     // raw K proj  [1024][512]
__device__ float g_vp[QLEN * NKV * HD];     // raw V proj  [1024][512]
__device__ float g_qh[NH * QLEN * HD];      // roped Q (scaled), head-major [28][1024][128]
__device__ float g_kf[NKV * KVLEN * HD];    // full K [4][4096][128]
__device__ float g_vf[NKV * KVLEN * HD];    // full V [4][4096][128]
__device__ float g_attn[QLEN * HID];        // attention out, tf32-rounded bits

// ---------------------------------------------------------------------------
// PTX helpers
// ---------------------------------------------------------------------------
__device__ __forceinline__ unsigned f2tf32(float x) {
    unsigned r;
    asm("cvt.rna.tf32.f32 %0, %1;" : "=r"(r) : "f"(x));
    return r;
}
__device__ __forceinline__ void splitf(float x, unsigned& hi, unsigned& lo) {
    hi = f2tf32(x);
    lo = f2tf32(x - __uint_as_float(hi));
}
__device__ __forceinline__ void mma8(float* d, const unsigned* a, const unsigned* b) {
    asm volatile(
        "mma.sync.aligned.m16n8k8.row.col.f32.tf32.tf32.f32 "
        "{%0,%1,%2,%3}, {%4,%5,%6,%7}, {%8,%9}, {%0,%1,%2,%3};\n"
        : "+f"(d[0]), "+f"(d[1]), "+f"(d[2]), "+f"(d[3])
        : "r"(a[0]), "r"(a[1]), "r"(a[2]), "r"(a[3]), "r"(b[0]), "r"(b[1]));
}
__device__ __forceinline__ void cp16(const float* smem_dst, const float* gmem_src) {
    unsigned s = (unsigned)__cvta_generic_to_shared(smem_dst);
    asm volatile("cp.async.cg.shared.global [%0], [%1], 16;\n"
                 :: "r"(s), "l"(__cvta_generic_to_global(gmem_src)));
}
#define CP_COMMIT() asm volatile("cp.async.commit_group;\n")
#define CP_WAIT0()  asm volatile("cp.async.wait_group 0;\n")

// ---------------------------------------------------------------------------
// tf32 GEMM: 128x128 tile, BK=32, 256 threads (8 warps, 4x2), double-buffered
// cp.async.
//   SPLIT=3 -> tf32x3 (A and B split; near-fp32)
//   SPLIT=2 -> tf32x2 (A split hi/lo; B single-tf32 rounded)
//   SPLIT=1 -> single tf32; if APRE/BPRE the operand is already tf32-rounded
//              bits in gmem, so that side needs no conversion in the mainloop.
// A: MxK row-major, B: KxN row-major, C row-major.
// ---------------------------------------------------------------------------
#define AS_STR 36
#define BS_STR 136
#define AS_BUF (128 * AS_STR)
#define BS_BUF (32 * BS_STR)
#define GEMM_SMEM_BYTES ((2 * AS_BUF + 2 * BS_BUF) * 4)

template <int SPLIT, bool APRE, bool BPRE>
__device__ __forceinline__ void gemm_tf32(const float* __restrict__ A,
                                          const float* __restrict__ B,
                                          const float* __restrict__ bias,
                                          float* __restrict__ C,
                                          int N, int K, int bm, int bn) {
    extern __shared__ float sm[];
    float* AS = sm;
    float* BS = sm + 2 * AS_BUF;

    const int tid = threadIdx.x;
    const int lane = tid & 31;
    const int wid = tid >> 5;
    const int wm = (wid >> 1) * 32;
    const int wn = (wid & 1) * 64;
    const int g = lane >> 2;
    const int c = lane & 3;

    float acc[2][8][4];
#pragma unroll
    for (int mt = 0; mt < 2; mt++)
#pragma unroll
        for (int nt = 0; nt < 8; nt++)
#pragma unroll
            for (int j = 0; j < 4; j++) acc[mt][nt][j] = 0.f;

    const int nk = K / 32;

    // prefetch tile 0
    {
        float* as = AS;
        float* bs = BS;
#pragma unroll
        for (int i = 0; i < 4; i++) {
            int idx = tid + i * 256;
            int r = idx >> 3, cc = (idx & 7) * 4;
            cp16(&as[r * AS_STR + cc], &A[(size_t)(bm + r) * K + cc]);
        }
#pragma unroll
        for (int i = 0; i < 4; i++) {
            int idx = tid + i * 256;
            int r = idx >> 5, cc = (idx & 31) * 4;
            cp16(&bs[r * BS_STR + cc], &B[(size_t)r * N + bn + cc]);
        }
        CP_COMMIT();
    }

    for (int it = 0; it < nk; it++) {
        CP_WAIT0();
        __syncthreads();
        if (it + 1 < nk) {
            int k0 = (it + 1) * 32;
            float* as = AS + ((it + 1) & 1) * AS_BUF;
            float* bs = BS + ((it + 1) & 1) * BS_BUF;
#pragma unroll
            for (int i = 0; i < 4; i++) {
                int idx = tid + i * 256;
                int r = idx >> 3, cc = (idx & 7) * 4;
                cp16(&as[r * AS_STR + cc], &A[(size_t)(bm + r) * K + k0 + cc]);
            }
#pragma unroll
            for (int i = 0; i < 4; i++) {
                int idx = tid + i * 256;
                int r = idx >> 5, cc = (idx & 31) * 4;
                cp16(&bs[r * BS_STR + cc], &B[(size_t)(k0 + r) * N + bn + cc]);
            }
            CP_COMMIT();
        }
        const float* as = AS + (it & 1) * AS_BUF;
        const float* bs = BS + (it & 1) * BS_BUF;

#pragma unroll
        for (int kt = 0; kt < 4; kt++) {
            unsigned ah[2][4], al[2][4];
#pragma unroll
            for (int mt = 0; mt < 2; mt++) {
                int rb = wm + mt * 16;
                float f0 = as[(rb + g) * AS_STR + kt * 8 + c];
                float f1 = as[(rb + g + 8) * AS_STR + kt * 8 + c];
                float f2 = as[(rb + g) * AS_STR + kt * 8 + c + 4];
                float f3 = as[(rb + g + 8) * AS_STR + kt * 8 + c + 4];
                if (SPLIT >= 2) {
                    splitf(f0, ah[mt][0], al[mt][0]);
                    splitf(f1, ah[mt][1], al[mt][1]);
                    splitf(f2, ah[mt][2], al[mt][2]);
                    splitf(f3, ah[mt][3], al[mt][3]);
                } else if (APRE) {
                    ah[mt][0] = __float_as_uint(f0); ah[mt][1] = __float_as_uint(f1);
                    ah[mt][2] = __float_as_uint(f2); ah[mt][3] = __float_as_uint(f3);
                } else {
                    ah[mt][0] = f2tf32(f0); ah[mt][1] = f2tf32(f1);
                    ah[mt][2] = f2tf32(f2); ah[mt][3] = f2tf32(f3);
                }
            }
#pragma unroll
            for (int nt = 0; nt < 8; nt++) {
                float f0 = bs[(kt * 8 + c) * BS_STR + wn + nt * 8 + g];
                float f1 = bs[(kt * 8 + c + 4) * BS_STR + wn + nt * 8 + g];
                unsigned bh[2], bl[2];
                if (SPLIT == 3) {
                    splitf(f0, bh[0], bl[0]);
                    splitf(f1, bh[1], bl[1]);
                } else if (BPRE) {
                    bh[0] = __float_as_uint(f0); bh[1] = __float_as_uint(f1);
                } else {
                    bh[0] = f2tf32(f0); bh[1] = f2tf32(f1);
                }
#pragma unroll
                for (int mt = 0; mt < 2; mt++) {
                    mma8(acc[mt][nt], ah[mt], bh);
                    if (SPLIT >= 2) mma8(acc[mt][nt], al[mt], bh);
                    if (SPLIT == 3) mma8(acc[mt][nt], ah[mt], bl);
                }
            }
        }
    }

    // epilogue
#pragma unroll
    for (int mt = 0; mt < 2; mt++) {
        int r0 = bm + wm + mt * 16 + g;
#pragma unroll
        for (int nt = 0; nt < 8; nt++) {
            int c0 = bn + wn + nt * 8 + 2 * c;
            float2 v0 = make_float2(acc[mt][nt][0], acc[mt][nt][1]);
            float2 v1 = make_float2(acc[mt][nt][2], acc[mt][nt][3]);
            if (bias) {
                float b0 = bias[c0], b1 = bias[c0 + 1];
                v0.x += b0; v0.y += b1;
                v1.x += b0; v1.y += b1;
            }
            *(float2*)&C[(size_t)r0 * N + c0] = v0;
            *(float2*)&C[(size_t)(r0 + 8) * N + c0] = v1;
        }
    }
}

// Fused QKV projection: bx<28 -> Q (x2), [28,32) -> K (x2), [32,36) -> V (x1).
// Per the calibrated error model each single-tf32 truncation on the logit
// path costs ~1e-4 rel_err; x2 on Q/K projections keeps total ~6.5e-4.
__global__ __launch_bounds__(256, 2) void qkv_gemm_kernel(
    const float* __restrict__ X,
    const float* __restrict__ Wq, const float* __restrict__ bq,
    const float* __restrict__ Wk, const float* __restrict__ bk,
    const float* __restrict__ Wv, const float* __restrict__ bv,
    float* __restrict__ Qo, float* __restrict__ Ko, float* __restrict__ Vo) {
    int bx = blockIdx.x;
    if (bx < 28) {
        gemm_tf32<2, false, false>(X, Wq, bq, Qo, HID, HID, blockIdx.y * 128, bx * 128);
    } else if (bx < 32) {
        gemm_tf32<2, false, false>(X, Wk, bk, Ko, NKV * HD, HID, blockIdx.y * 128, (bx - 28) * 128);
    } else {
        gemm_tf32<1, false, false>(X, Wv, bv, Vo, NKV * HD, HID, blockIdx.y * 128, (bx - 32) * 128);
    }
}

// O-projection: A (g_attn) is tf32-pre-rounded by the attention epilogue.
__global__ __launch_bounds__(256, 2) void out_gemm_kernel(
    const float* __restrict__ A, const float* __restrict__ Wo,
    float* __restrict__ C) {
    gemm_tf32<1, true, false>(A, Wo, nullptr, C, HID, HID, blockIdx.y * 128, blockIdx.x * 128);
}

// ---------------------------------------------------------------------------
// Copy cached prefix into full KV buffers
// ---------------------------------------------------------------------------
__global__ void copy_cache_kernel(const float* __restrict__ kc,
                                  const float* __restrict__ vc,
                                  float* __restrict__ Kf,
                                  float* __restrict__ Vf) {
    const int per_h = PAST * HD / 4;
    int i = blockIdx.x * blockDim.x + threadIdx.x;
    if (i >= NKV * per_h) return;
    int kh = i / per_h;
    int r = i - kh * per_h;
    const float4* ks = (const float4*)kc;
    const float4* vs = (const float4*)vc;
    float4* kd = (float4*)(Kf + (size_t)kh * KVLEN * HD);
    float4* vd = (float4*)(Vf + (size_t)kh * KVLEN * HD);
    kd[r] = ks[i];
    vd[r] = vs[i];
}

// ---------------------------------------------------------------------------
// RoPE + scatter. Q gets 1/sqrt(128) folded in. One block per token m.
// ---------------------------------------------------------------------------
__global__ void rope_kernel(const float* __restrict__ Qp,
                            const float* __restrict__ Kp,
                            const float* __restrict__ Vp,
                            const int* __restrict__ pos,
                            float* __restrict__ Qh,
                            float* __restrict__ Kf,
                            float* __restrict__ Vf) {
    const int m = blockIdx.x;
    const float p = (float)pos[m];
    const float qscale = 0.08838834764831845f;  // 1/sqrt(128)

    for (int idx = threadIdx.x; idx < NH * 64; idx += blockDim.x) {
        int h = idx >> 6;
        int d = idx & 63;
        float invf = (float)exp(-(double)d * (1.3815510557964274e+01 / 64.0));
        float ang = p * invf;
        float s, c;
        sincosf(ang, &s, &c);
        float x1 = Qp[(size_t)m * HID + h * HD + d];
        float x2 = Qp[(size_t)m * HID + h * HD + d + 64];
        float o1 = (x1 * c - x2 * s) * qscale;
        float o2 = (x2 * c + x1 * s) * qscale;
        float* dst = Qh + ((size_t)h * QLEN + m) * HD;
        dst[d] = o1;
        dst[d + 64] = o2;
    }
    for (int idx = threadIdx.x; idx < NKV * 64; idx += blockDim.x) {
        int kh = idx >> 6;
        int d = idx & 63;
        float invf = (float)exp(-(double)d * (1.3815510557964274e+01 / 64.0));
        float ang = p * invf;
        float s, c;
        sincosf(ang, &s, &c);
        float x1 = Kp[(size_t)m * (NKV * HD) + kh * HD + d];
        float x2 = Kp[(size_t)m * (NKV * HD) + kh * HD + d + 64];
        float* kd = Kf + ((size_t)kh * KVLEN + PAST + m) * HD;
        kd[d] = x1 * c - x2 * s;
        kd[d + 64] = x2 * c + x1 * s;
        float* vd = Vf + ((size_t)kh * KVLEN + PAST + m) * HD;
        vd[d] = Vp[(size_t)m * (NKV * HD) + kh * HD + d];
        vd[d + 64] = Vp[(size_t)m * (NKV * HD) + kh * HD + d + 64];
    }
}

// ---------------------------------------------------------------------------
// Flash attention, tf32 tensor-core. BQ=64, BKV=32, 128 threads (4 warps,
// each warp owns 16 q-rows). 2 CTAs/SM (smem 77.3 KB, launch_bounds(128,2))
// so one CTA's MMA phases hide the other's softmax/barrier stalls, and the
// 448-block grid balances the causal-length skew.
// S=QK^T uses tf32x2 (Q split hi/lo, K single), P.V single tf32. K and V
// converted to tf32 ONCE at smem store. Epilogue writes tf32-rounded output.
// grid: (16 q-tiles, 28 heads), longest-first.
// ---------------------------------------------------------------------------
#define ATH 128
#define QS_STR 132
#define KS_STR 132
#define VS_STR 136
#define PS_STR 36
#define QS_FLOATS (64 * QS_STR)
#define KS_FLOATS (32 * KS_STR)
#define VS_FLOATS (32 * VS_STR)
#define PS_FLOATS (64 * PS_STR)
#define ATTN_SMEM_BYTES ((QS_FLOATS + KS_FLOATS + VS_FLOATS + PS_FLOATS) * 4)

__global__ __launch_bounds__(ATH, 2) void attn_kernel(
    const float* __restrict__ Qh, const float* __restrict__ Kf,
    const float* __restrict__ Vf, float* __restrict__ Aout) {
    extern __shared__ float sm[];
    float* QS = sm;                    // fp32 Q tile [64][132]
    float* KH = QS + QS_FLOATS;        // tf32 bits of K [32][132]
    float* VT = KH + KS_FLOATS;        // tf32 bits of V [32][136]
    float* PS = VT + VS_FLOATS;        // tf32 bits of P [64][36]

    const int tid = threadIdx.x;
    const int lane = tid & 31;
    const int w = tid >> 5;       // 4 warps, warp owns rows [w*16, w*16+16)
    const int g = lane >> 2;      // 0..7
    const int c = lane & 3;       // 0..3
    const int h = blockIdx.y;
    const int qi = (int)gridDim.x - 1 - (int)blockIdx.x;  // longest blocks first
    const int m0 = qi * 64;
    const int kvh = h / NREP;

    // ---- prologue: load Q tile [64][128] into QS (fp32, persists)
    {
        const float4* qb = (const float4*)(Qh + ((size_t)h * QLEN + m0) * HD);
#pragma unroll
        for (int i = 0; i < 16; i++) {
            int idx = tid + i * ATH;
            int r = idx >> 5, c4 = idx & 31;
            *(float4*)&QS[r * QS_STR + c4 * 4] = qb[idx];
        }
    }
    __syncthreads();

    const int ntiles = 96 + 2 * qi + 2;   // kv 0 .. PAST + m0 + 64, in 32-steps

    float mrow[2] = {-1e30f, -1e30f};
    float lrow[2] = {0.f, 0.f};
    float o[16][4];
#pragma unroll
    for (int dt = 0; dt < 16; dt++)
#pragma unroll
        for (int j = 0; j < 4; j++) o[dt][j] = 0.f;

    // register prefetch of tile 0 (32x128 K + V = 8 float4 each at 128 thr)
    float4 kq[8], vq[8];
    {
        const float4* kb = (const float4*)(Kf + ((size_t)kvh * KVLEN) * HD);
        const float4* vb = (const float4*)(Vf + ((size_t)kvh * KVLEN) * HD);
#pragma unroll
        for (int i = 0; i < 8; i++) { kq[i] = kb[tid + i * ATH]; vq[i] = vb[tid + i * ATH]; }
    }

    for (int t = 0; t < ntiles; t++) {
        __syncthreads();   // all readers of previous K/V tile done
        // ---- store prefetched tile to smem, converting K and V to tf32 once
#pragma unroll
        for (int i = 0; i < 8; i++) {
            int idx = tid + i * ATH;
            int r = idx >> 5, c4 = (idx & 31) * 4;
            *(float4*)&KH[r * KS_STR + c4] = make_float4(
                __uint_as_float(f2tf32(kq[i].x)), __uint_as_float(f2tf32(kq[i].y)),
                __uint_as_float(f2tf32(kq[i].z)), __uint_as_float(f2tf32(kq[i].w)));
            *(float4*)&VT[r * VS_STR + c4] = make_float4(
                __uint_as_float(f2tf32(vq[i].x)), __uint_as_float(f2tf32(vq[i].y)),
                __uint_as_float(f2tf32(vq[i].z)), __uint_as_float(f2tf32(vq[i].w)));
        }
        __syncthreads();
        // prefetch next tile (hidden under MMA work)
        if (t + 1 < ntiles) {
            const float4* kb = (const float4*)(Kf + ((size_t)kvh * KVLEN + (t + 1) * 32) * HD);
            const float4* vb = (const float4*)(Vf + ((size_t)kvh * KVLEN + (t + 1) * 32) * HD);
#pragma unroll
            for (int i = 0; i < 8; i++) { kq[i] = kb[tid + i * ATH]; vq[i] = vb[tid + i * ATH]; }
        }

        // ---- S = Q K^T (tf32x2: Q hi/lo, K single), per warp: 16 x 32
        float s[4][4];
#pragma unroll
        for (int nt = 0; nt < 4; nt++)
#pragma unroll
            for (int j = 0; j < 4; j++) s[nt][j] = 0.f;

        const float* QSw = QS + (w * 16) * QS_STR;
#pragma unroll 2
        for (int kt = 0; kt < 16; kt++) {
            unsigned ah[4], al[4];
            splitf(QSw[g * QS_STR + kt * 8 + c],            ah[0], al[0]);
            splitf(QSw[(g + 8) * QS_STR + kt * 8 + c],      ah[1], al[1]);
            splitf(QSw[g * QS_STR + kt * 8 + c + 4],        ah[2], al[2]);
            splitf(QSw[(g + 8) * QS_STR + kt * 8 + c + 4],  ah[3], al[3]);
#pragma unroll
            for (int nt = 0; nt < 4; nt++) {
                unsigned bh[2];
                bh[0] = __float_as_uint(KH[(nt * 8 + g) * KS_STR + kt * 8 + c]);
                bh[1] = __float_as_uint(KH[(nt * 8 + g) * KS_STR + kt * 8 + c + 4]);
                mma8(s[nt], ah, bh);
                mma8(s[nt], al, bh);
            }
        }

        // ---- causal mask (only last two tiles touch the diagonal)
        if (t >= ntiles - 2) {
            int base_col = t * 32;
            int lim0 = PAST + m0 + w * 16 + g;
            int lim1 = lim0 + 8;
#pragma unroll
            for (int nt = 0; nt < 4; nt++) {
                int c0 = base_col + nt * 8 + 2 * c;
                if (c0 > lim0)     s[nt][0] = -1e30f;
                if (c0 + 1 > lim0) s[nt][1] = -1e30f;
                if (c0 > lim1)     s[nt][2] = -1e30f;
                if (c0 + 1 > lim1) s[nt][3] = -1e30f;
            }
        }

        // ---- online softmax (rows g and g+8; reductions over the 4-lane group)
#pragma unroll
        for (int rr = 0; rr < 2; rr++) {
            float mx = -1e30f;
#pragma unroll
            for (int nt = 0; nt < 4; nt++)
                mx = fmaxf(mx, fmaxf(s[nt][2 * rr], s[nt][2 * rr + 1]));
            mx = fmaxf(mx, __shfl_xor_sync(0xffffffffu, mx, 1));
            mx = fmaxf(mx, __shfl_xor_sync(0xffffffffu, mx, 2));
            float mn = fmaxf(mrow[rr], mx);
            float alpha = __expf(mrow[rr] - mn);
            mrow[rr] = mn;
            float ls = 0.f;
#pragma unroll
            for (int nt = 0; nt < 4; nt++) {
                float e0 = __expf(s[nt][2 * rr] - mn);
                float e1 = __expf(s[nt][2 * rr + 1] - mn);
                s[nt][2 * rr] = e0;
                s[nt][2 * rr + 1] = e1;
                ls += e0 + e1;
            }
            ls += __shfl_xor_sync(0xffffffffu, ls, 1);
            ls += __shfl_xor_sync(0xffffffffu, ls, 2);
            lrow[rr] = lrow[rr] * alpha + ls;
#pragma unroll
            for (int dt = 0; dt < 16; dt++) {
                o[dt][2 * rr] *= alpha;
                o[dt][2 * rr + 1] *= alpha;
            }
        }

        // ---- store P to smem as tf32 bit-patterns
        {
            float* p0 = PS + (w * 16 + g) * PS_STR;
            float* p1 = PS + (w * 16 + g + 8) * PS_STR;
#pragma unroll
            for (int nt = 0; nt < 4; nt++) {
                *(float2*)&p0[nt * 8 + 2 * c] = make_float2(
                    __uint_as_float(f2tf32(s[nt][0])), __uint_as_float(f2tf32(s[nt][1])));
                *(float2*)&p1[nt * 8 + 2 * c] = make_float2(
                    __uint_as_float(f2tf32(s[nt][2])), __uint_as_float(f2tf32(s[nt][3])));
            }
        }
        __syncwarp();

        // ---- O += P @ V (single tf32), per warp: 16 x 128
        const float* PSw = PS + (w * 16) * PS_STR;
#pragma unroll
        for (int ktv = 0; ktv < 4; ktv++) {
            unsigned a[4];
            a[0] = __float_as_uint(PSw[g * PS_STR + ktv * 8 + c]);
            a[1] = __float_as_uint(PSw[(g + 8) * PS_STR + ktv * 8 + c]);
            a[2] = __float_as_uint(PSw[g * PS_STR + ktv * 8 + c + 4]);
            a[3] = __float_as_uint(PSw[(g + 8) * PS_STR + ktv * 8 + c + 4]);
#pragma unroll
            for (int dt = 0; dt < 16; dt++) {
                unsigned b[2];
                b[0] = __float_as_uint(VT[(ktv * 8 + c) * VS_STR + dt * 8 + g]);
                b[1] = __float_as_uint(VT[(ktv * 8 + c + 4) * VS_STR + dt * 8 + g]);
                mma8(o[dt], a, b);
            }
        }
    }

    // ---- normalize and write [1024][3584], pre-rounded to tf32 for O-proj
#pragma unroll
    for (int rr = 0; rr < 2; rr++) {
        float inv = 1.0f / lrow[rr];
        int row = m0 + w * 16 + g + rr * 8;
        float* dst = Aout + (size_t)row * HID + h * HD;
#pragma unroll
        for (int dt = 0; dt < 16; dt++) {
            *(float2*)&dst[dt * 8 + 2 * c] = make_float2(
                __uint_as_float(f2tf32(o[dt][2 * rr] * inv)),
                __uint_as_float(f2tf32(o[dt][2 * rr + 1] * inv)));
        }
    }
}

// ---------------------------------------------------------------------------
// Launch
// ---------------------------------------------------------------------------
extern "C" void kernel_launch(void* const* d_in, const int* in_sizes, int n_in,
                              void* d_out, int out_size) {
    (void)in_sizes; (void)n_in; (void)out_size;
    const float* X  = (const float*)d_in[0];
    const float* kc = (const float*)d_in[1];
    const float* vc = (const float*)d_in[2];
    const float* Wq = (const float*)d_in[3];
    const float* bq = (const float*)d_in[4];
    const float* Wk = (const float*)d_in[5];
    const float* bk = (const float*)d_in[6];
    const float* Wv = (const float*)d_in[7];
    const float* bv = (const float*)d_in[8];
    const float* Wo = (const float*)d_in[9];
    const int*  pos = (const int*)d_in[10];
    float* out = (float*)d_out;

    float *qp, *kp, *vp, *qh, *kf, *vf, *attn;
    cudaGetSymbolAddress((void**)&qp, g_qp);
    cudaGetSymbolAddress((void**)&kp, g_kp);
    cudaGetSymbolAddress((void**)&vp, g_vp);
    cudaGetSymbolAddress((void**)&qh, g_qh);
    cudaGetSymbolAddress((void**)&kf, g_kf);
    cudaGetSymbolAddress((void**)&vf, g_vf);
    cudaGetSymbolAddress((void**)&attn, g_attn);

    static bool attr_set = false;
    if (!attr_set) {
        cudaFuncSetAttribute(qkv_gemm_kernel,
                             cudaFuncAttributeMaxDynamicSharedMemorySize, GEMM_SMEM_BYTES);
        cudaFuncSetAttribute(out_gemm_kernel,
                             cudaFuncAttributeMaxDynamicSharedMemorySize, GEMM_SMEM_BYTES);
        cudaFuncSetAttribute(attn_kernel,
                             cudaFuncAttributeMaxDynamicSharedMemorySize, ATTN_SMEM_BYTES);
        attr_set = true;
    }

    // 1) fused QKV projection (Q,K: tf32x2; V: single tf32)
    qkv_gemm_kernel<<<dim3(36, 8), 256, GEMM_SMEM_BYTES>>>(
        X, Wq, bq, Wk, bk, Wv, bv, qp, kp, vp);

    // 2) KV cache prefix copy
    {
        int total = NKV * PAST * HD / 4;
        copy_cache_kernel<<<(total + 255) / 256, 256>>>(kc, vc, kf, vf);
    }

    // 3) RoPE + scatter into head-major / full-KV layouts
    rope_kernel<<<QLEN, 256>>>(qp, kp, vp, pos, qh, kf, vf);

    // 4) flash attention (tensor-core, 2 CTAs/SM, 448 blocks)
    attn_kernel<<<dim3(16, NH), ATH, ATTN_SMEM_BYTES>>>(qh, kf, vf, attn);

    // 5) output projection (A pre-rounded by attn epilogue; Wo cvt per-use)
    out_gemm_kernel<<<dim3(28, 8), 256, GEMM_SMEM_BYTES>>>(attn, Wo, out);
}

// round 17
// speedup vs baseline: 2.6196x; 1.0939x over previous
#include <cuda_runtime.h>
#include <cuda_bf16.h>
#include <math.h>
#include <stdint.h>

// ---------------------------------------------------------------------------
// Problem constants
// ---------------------------------------------------------------------------
#define QLEN 1024
#define HID 3584
#define NH 28
#define NKV 4
#define HD 128
#define PAST 3072
#define KVLEN 4096          // PAST + QLEN
#define NREP 7              // NH / NKV

// ---------------------------------------------------------------------------
// Scratch (no allocations allowed -> __device__ globals)
// ---------------------------------------------------------------------------
__device__ float g_qp[QLEN * HID];          // raw Q proj  [1024][3584]
__device__ float g_kp[QLEN * NKV * HD];     // raw K proj  [1024][512]
__device__ float g_vp[QLEN * NKV * HD];     // raw V proj  [1024][512]
__device__ float g_qh[NH * QLEN * HD];      // roped Q (scaled), head-major [28][1024][128]
__device__ float g_kf[NKV * KVLEN * HD];    // full K, tf32-rounded bits [4][4096][128]
__device__ float g_vf[NKV * KVLEN * HD];    // full V, tf32-rounded bits [4][4096][128]
__device__ float g_attn[QLEN * HID];        // attention out, tf32-rounded bits

// ---------------------------------------------------------------------------
// PTX helpers
// ---------------------------------------------------------------------------
__device__ __forceinline__ unsigned f2tf32(float x) {
    unsigned r;
    asm("cvt.rna.tf32.f32 %0, %1;" : "=r"(r) : "f"(x));
    return r;
}
__device__ __forceinline__ float f2tf32f(float x) {
    return __uint_as_float(f2tf32(x));
}
__device__ __forceinline__ void splitf(float x, unsigned& hi, unsigned& lo) {
    hi = f2tf32(x);
    lo = f2tf32(x - __uint_as_float(hi));
}
__device__ __forceinline__ void mma8(float* d, const unsigned* a, const unsigned* b) {
    asm volatile(
        "mma.sync.aligned.m16n8k8.row.col.f32.tf32.tf32.f32 "
        "{%0,%1,%2,%3}, {%4,%5,%6,%7}, {%8,%9}, {%0,%1,%2,%3};\n"
        : "+f"(d[0]), "+f"(d[1]), "+f"(d[2]), "+f"(d[3])
        : "r"(a[0]), "r"(a[1]), "r"(a[2]), "r"(a[3]), "r"(b[0]), "r"(b[1]));
}
__device__ __forceinline__ void cp16(const float* smem_dst, const float* gmem_src) {
    unsigned s = (unsigned)__cvta_generic_to_shared(smem_dst);
    asm volatile("cp.async.cg.shared.global [%0], [%1], 16;\n"
                 :: "r"(s), "l"(__cvta_generic_to_global(gmem_src)));
}
#define CP_COMMIT() asm volatile("cp.async.commit_group;\n")
#define CP_WAIT0()  asm volatile("cp.async.wait_group 0;\n")

// ---------------------------------------------------------------------------
// tf32 GEMM: 128x128 tile, BK=32, 256 threads (8 warps, 4x2), double-buffered
// cp.async.
//   SPLIT=3 -> tf32x3 (A and B split; near-fp32)
//   SPLIT=2 -> tf32x2 (A split hi/lo; B single-tf32 rounded)
//   SPLIT=1 -> single tf32; if APRE/BPRE the operand is already tf32-rounded
//              bits in gmem, so that side needs no conversion in the mainloop.
// A: MxK row-major, B: KxN row-major, C row-major.
// ---------------------------------------------------------------------------
#define AS_STR 36
#define BS_STR 136
#define AS_BUF (128 * AS_STR)
#define BS_BUF (32 * BS_STR)
#define GEMM_SMEM_BYTES ((2 * AS_BUF + 2 * BS_BUF) * 4)

template <int SPLIT, bool APRE, bool BPRE>
__device__ __forceinline__ void gemm_tf32(const float* __restrict__ A,
                                          const float* __restrict__ B,
                                          const float* __restrict__ bias,
                                          float* __restrict__ C,
                                          int N, int K, int bm, int bn) {
    extern __shared__ float sm[];
    float* AS = sm;
    float* BS = sm + 2 * AS_BUF;

    const int tid = threadIdx.x;
    const int lane = tid & 31;
    const int wid = tid >> 5;
    const int wm = (wid >> 1) * 32;
    const int wn = (wid & 1) * 64;
    const int g = lane >> 2;
    const int c = lane & 3;

    float acc[2][8][4];
#pragma unroll
    for (int mt = 0; mt < 2; mt++)
#pragma unroll
        for (int nt = 0; nt < 8; nt++)
#pragma unroll
            for (int j = 0; j < 4; j++) acc[mt][nt][j] = 0.f;

    const int nk = K / 32;

    // prefetch tile 0
    {
        float* as = AS;
        float* bs = BS;
#pragma unroll
        for (int i = 0; i < 4; i++) {
            int idx = tid + i * 256;
            int r = idx >> 3, cc = (idx & 7) * 4;
            cp16(&as[r * AS_STR + cc], &A[(size_t)(bm + r) * K + cc]);
        }
#pragma unroll
        for (int i = 0; i < 4; i++) {
            int idx = tid + i * 256;
            int r = idx >> 5, cc = (idx & 31) * 4;
            cp16(&bs[r * BS_STR + cc], &B[(size_t)r * N + bn + cc]);
        }
        CP_COMMIT();
    }

    for (int it = 0; it < nk; it++) {
        CP_WAIT0();
        __syncthreads();
        if (it + 1 < nk) {
            int k0 = (it + 1) * 32;
            float* as = AS + ((it + 1) & 1) * AS_BUF;
            float* bs = BS + ((it + 1) & 1) * BS_BUF;
#pragma unroll
            for (int i = 0; i < 4; i++) {
                int idx = tid + i * 256;
                int r = idx >> 3, cc = (idx & 7) * 4;
                cp16(&as[r * AS_STR + cc], &A[(size_t)(bm + r) * K + k0 + cc]);
            }
#pragma unroll
            for (int i = 0; i < 4; i++) {
                int idx = tid + i * 256;
                int r = idx >> 5, cc = (idx & 31) * 4;
                cp16(&bs[r * BS_STR + cc], &B[(size_t)(k0 + r) * N + bn + cc]);
            }
            CP_COMMIT();
        }
        const float* as = AS + (it & 1) * AS_BUF;
        const float* bs = BS + (it & 1) * BS_BUF;

#pragma unroll
        for (int kt = 0; kt < 4; kt++) {
            unsigned ah[2][4], al[2][4];
#pragma unroll
            for (int mt = 0; mt < 2; mt++) {
                int rb = wm + mt * 16;
                float f0 = as[(rb + g) * AS_STR + kt * 8 + c];
                float f1 = as[(rb + g + 8) * AS_STR + kt * 8 + c];
                float f2 = as[(rb + g) * AS_STR + kt * 8 + c + 4];
                float f3 = as[(rb + g + 8) * AS_STR + kt * 8 + c + 4];
                if (SPLIT >= 2) {
                    splitf(f0, ah[mt][0], al[mt][0]);
                    splitf(f1, ah[mt][1], al[mt][1]);
                    splitf(f2, ah[mt][2], al[mt][2]);
                    splitf(f3, ah[mt][3], al[mt][3]);
                } else if (APRE) {
                    ah[mt][0] = __float_as_uint(f0); ah[mt][1] = __float_as_uint(f1);
                    ah[mt][2] = __float_as_uint(f2); ah[mt][3] = __float_as_uint(f3);
                } else {
                    ah[mt][0] = f2tf32(f0); ah[mt][1] = f2tf32(f1);
                    ah[mt][2] = f2tf32(f2); ah[mt][3] = f2tf32(f3);
                }
            }
#pragma unroll
            for (int nt = 0; nt < 8; nt++) {
                float f0 = bs[(kt * 8 + c) * BS_STR + wn + nt * 8 + g];
                float f1 = bs[(kt * 8 + c + 4) * BS_STR + wn + nt * 8 + g];
                unsigned bh[2], bl[2];
                if (SPLIT == 3) {
                    splitf(f0, bh[0], bl[0]);
                    splitf(f1, bh[1], bl[1]);
                } else if (BPRE) {
                    bh[0] = __float_as_uint(f0); bh[1] = __float_as_uint(f1);
                } else {
                    bh[0] = f2tf32(f0); bh[1] = f2tf32(f1);
                }
#pragma unroll
                for (int mt = 0; mt < 2; mt++) {
                    mma8(acc[mt][nt], ah[mt], bh);
                    if (SPLIT >= 2) mma8(acc[mt][nt], al[mt], bh);
                    if (SPLIT == 3) mma8(acc[mt][nt], ah[mt], bl);
                }
            }
        }
    }

    // epilogue
#pragma unroll
    for (int mt = 0; mt < 2; mt++) {
        int r0 = bm + wm + mt * 16 + g;
#pragma unroll
        for (int nt = 0; nt < 8; nt++) {
            int c0 = bn + wn + nt * 8 + 2 * c;
            float2 v0 = make_float2(acc[mt][nt][0], acc[mt][nt][1]);
            float2 v1 = make_float2(acc[mt][nt][2], acc[mt][nt][3]);
            if (bias) {
                float b0 = bias[c0], b1 = bias[c0 + 1];
                v0.x += b0; v0.y += b1;
                v1.x += b0; v1.y += b1;
            }
            *(float2*)&C[(size_t)r0 * N + c0] = v0;
            *(float2*)&C[(size_t)(r0 + 8) * N + c0] = v1;
        }
    }
}

// Fused QKV projection: bx<28 -> Q (x2), [28,32) -> K (x2), [32,36) -> V (x1).
__global__ __launch_bounds__(256, 2) void qkv_gemm_kernel(
    const float* __restrict__ X,
    const float* __restrict__ Wq, const float* __restrict__ bq,
    const float* __restrict__ Wk, const float* __restrict__ bk,
    const float* __restrict__ Wv, const float* __restrict__ bv,
    float* __restrict__ Qo, float* __restrict__ Ko, float* __restrict__ Vo) {
    int bx = blockIdx.x;
    if (bx < 28) {
        gemm_tf32<2, false, false>(X, Wq, bq, Qo, HID, HID, blockIdx.y * 128, bx * 128);
    } else if (bx < 32) {
        gemm_tf32<2, false, false>(X, Wk, bk, Ko, NKV * HD, HID, blockIdx.y * 128, (bx - 28) * 128);
    } else {
        gemm_tf32<1, false, false>(X, Wv, bv, Vo, NKV * HD, HID, blockIdx.y * 128, (bx - 32) * 128);
    }
}

// O-projection: A (g_attn) is tf32-pre-rounded by the attention epilogue.
__global__ __launch_bounds__(256, 2) void out_gemm_kernel(
    const float* __restrict__ A, const float* __restrict__ Wo,
    float* __restrict__ C) {
    gemm_tf32<1, true, false>(A, Wo, nullptr, C, HID, HID, blockIdx.y * 128, blockIdx.x * 128);
}

// ---------------------------------------------------------------------------
// Copy cached prefix into full KV buffers, rounding to tf32 bits at write.
// (Same cvt.rna the attention kernel used to do per-tile — bit-identical,
// but done once per value instead of once per consuming q-head-tile.)
// ---------------------------------------------------------------------------
__global__ void copy_cache_kernel(const float* __restrict__ kc,
                                  const float* __restrict__ vc,
                                  float* __restrict__ Kf,
                                  float* __restrict__ Vf) {
    const int per_h = PAST * HD / 4;
    int i = blockIdx.x * blockDim.x + threadIdx.x;
    if (i >= NKV * per_h) return;
    int kh = i / per_h;
    int r = i - kh * per_h;
    const float4* ks = (const float4*)kc;
    const float4* vs = (const float4*)vc;
    float4* kd = (float4*)(Kf + (size_t)kh * KVLEN * HD);
    float4* vd = (float4*)(Vf + (size_t)kh * KVLEN * HD);
    float4 k = ks[i], v = vs[i];
    kd[r] = make_float4(f2tf32f(k.x), f2tf32f(k.y), f2tf32f(k.z), f2tf32f(k.w));
    vd[r] = make_float4(f2tf32f(v.x), f2tf32f(v.y), f2tf32f(v.z), f2tf32f(v.w));
}

// ---------------------------------------------------------------------------
// RoPE + scatter. Q gets 1/sqrt(128) folded in (stays fp32 for x2 split).
// K/V are written as tf32-rounded bits. One block per token m.
// ---------------------------------------------------------------------------
__global__ void rope_kernel(const float* __restrict__ Qp,
                            const float* __restrict__ Kp,
                            const float* __restrict__ Vp,
                            const int* __restrict__ pos,
                            float* __restrict__ Qh,
                            float* __restrict__ Kf,
                            float* __restrict__ Vf) {
    const int m = blockIdx.x;
    const float p = (float)pos[m];
    const float qscale = 0.08838834764831845f;  // 1/sqrt(128)

    for (int idx = threadIdx.x; idx < NH * 64; idx += blockDim.x) {
        int h = idx >> 6;
        int d = idx & 63;
        float invf = (float)exp(-(double)d * (1.3815510557964274e+01 / 64.0));
        float ang = p * invf;
        float s, c;
        sincosf(ang, &s, &c);
        float x1 = Qp[(size_t)m * HID + h * HD + d];
        float x2 = Qp[(size_t)m * HID + h * HD + d + 64];
        float o1 = (x1 * c - x2 * s) * qscale;
        float o2 = (x2 * c + x1 * s) * qscale;
        float* dst = Qh + ((size_t)h * QLEN + m) * HD;
        dst[d] = o1;
        dst[d + 64] = o2;
    }
    for (int idx = threadIdx.x; idx < NKV * 64; idx += blockDim.x) {
        int kh = idx >> 6;
        int d = idx & 63;
        float invf = (float)exp(-(double)d * (1.3815510557964274e+01 / 64.0));
        float ang = p * invf;
        float s, c;
        sincosf(ang, &s, &c);
        float x1 = Kp[(size_t)m * (NKV * HD) + kh * HD + d];
        float x2 = Kp[(size_t)m * (NKV * HD) + kh * HD + d + 64];
        float* kd = Kf + ((size_t)kh * KVLEN + PAST + m) * HD;
        kd[d] = f2tf32f(x1 * c - x2 * s);
        kd[d + 64] = f2tf32f(x2 * c + x1 * s);
        float* vd = Vf + ((size_t)kh * KVLEN + PAST + m) * HD;
        vd[d] = f2tf32f(Vp[(size_t)m * (NKV * HD) + kh * HD + d]);
        vd[d + 64] = f2tf32f(Vp[(size_t)m * (NKV * HD) + kh * HD + d + 64]);
    }
}

// ---------------------------------------------------------------------------
// Flash attention, tf32 tensor-core. BQ=128, BKV=64, 256 threads (8 warps,
// each warp owns 16 q-rows) — the R12 geometry, which measured fastest.
// S=QK^T uses tf32x2 (Q split hi/lo, K single), P.V single tf32. K and V
// arrive from gmem ALREADY tf32-rounded, so the tile store is a pure copy.
// Epilogue writes tf32-rounded output so O-proj's A side needs no cvt.
// grid: (8 q-tiles, 28 heads), longest-first. smem = 171 KB, 1 CTA/SM.
// ---------------------------------------------------------------------------
#define QS_STR 132
#define KS_STR 132
#define VS_STR 136
#define PS_STR 68
#define QS_FLOATS (128 * QS_STR)
#define KS_FLOATS (64 * KS_STR)
#define VS_FLOATS (64 * VS_STR)
#define PS_FLOATS (128 * PS_STR)
#define ATTN_SMEM_BYTES ((QS_FLOATS + KS_FLOATS + VS_FLOATS + PS_FLOATS) * 4)

__global__ __launch_bounds__(256, 1) void attn_kernel(
    const float* __restrict__ Qh, const float* __restrict__ Kf,
    const float* __restrict__ Vf, float* __restrict__ Aout) {
    extern __shared__ float sm[];
    float* QS = sm;                    // fp32 Q tile
    float* KH = QS + QS_FLOATS;        // tf32 bits of K (single)
    float* VT = KH + KS_FLOATS;        // tf32 bits of V
    float* PS = VT + VS_FLOATS;        // tf32 bits of P

    const int tid = threadIdx.x;
    const int lane = tid & 31;
    const int w = tid >> 5;       // 8 warps
    const int g = lane >> 2;      // 0..7
    const int c = lane & 3;       // 0..3
    const int h = blockIdx.y;
    const int qi = (int)gridDim.x - 1 - (int)blockIdx.x;  // longest blocks first
    const int m0 = qi * 128;
    const int kvh = h / NREP;

    // ---- prologue: load Q tile [128][128] into QS (fp32, persists)
    {
        const float4* qb = (const float4*)(Qh + ((size_t)h * QLEN + m0) * HD);
#pragma unroll
        for (int i = 0; i < 16; i++) {
            int idx = tid + i * 256;
            int r = idx >> 5, c4 = idx & 31;
            *(float4*)&QS[r * QS_STR + c4 * 4] = qb[idx];
        }
    }
    __syncthreads();

    const int ntiles = 48 + 2 * qi + 2;

    float mrow[2] = {-1e30f, -1e30f};
    float lrow[2] = {0.f, 0.f};
    float o[16][4];
#pragma unroll
    for (int dt = 0; dt < 16; dt++)
#pragma unroll
        for (int j = 0; j < 4; j++) o[dt][j] = 0.f;

    // register prefetch of tile 0
    float4 kq[8], vq[8];
    {
        const float4* kb = (const float4*)(Kf + ((size_t)kvh * KVLEN) * HD);
        const float4* vb = (const float4*)(Vf + ((size_t)kvh * KVLEN) * HD);
#pragma unroll
        for (int i = 0; i < 8; i++) { kq[i] = kb[tid + i * 256]; vq[i] = vb[tid + i * 256]; }
    }

    for (int t = 0; t < ntiles; t++) {
        __syncthreads();   // all readers of previous K/V tile done
        // ---- store prefetched tile to smem (already tf32 bits: pure copy)
#pragma unroll
        for (int i = 0; i < 8; i++) {
            int idx = tid + i * 256;
            int r = idx >> 5, c4 = (idx & 31) * 4;
            *(float4*)&KH[r * KS_STR + c4] = kq[i];
            *(float4*)&VT[r * VS_STR + c4] = vq[i];
        }
        __syncthreads();
        // prefetch next tile (hidden under MMA work)
        if (t + 1 < ntiles) {
            const float4* kb = (const float4*)(Kf + ((size_t)kvh * KVLEN + (t + 1) * 64) * HD);
            const float4* vb = (const float4*)(Vf + ((size_t)kvh * KVLEN + (t + 1) * 64) * HD);
#pragma unroll
            for (int i = 0; i < 8; i++) { kq[i] = kb[tid + i * 256]; vq[i] = vb[tid + i * 256]; }
        }

        // ---- S = Q K^T (tf32x2: Q hi/lo, K single), per warp: 16 x 64
        float s[8][4];
#pragma unroll
        for (int nt = 0; nt < 8; nt++)
#pragma unroll
            for (int j = 0; j < 4; j++) s[nt][j] = 0.f;

        const float* QSw = QS + (w * 16) * QS_STR;
#pragma unroll 2
        for (int kt = 0; kt < 16; kt++) {
            unsigned ah[4], al[4];
            splitf(QSw[g * QS_STR + kt * 8 + c],            ah[0], al[0]);
            splitf(QSw[(g + 8) * QS_STR + kt * 8 + c],      ah[1], al[1]);
            splitf(QSw[g * QS_STR + kt * 8 + c + 4],        ah[2], al[2]);
            splitf(QSw[(g + 8) * QS_STR + kt * 8 + c + 4],  ah[3], al[3]);
#pragma unroll
            for (int nt = 0; nt < 8; nt++) {
                unsigned bh[2];
                bh[0] = __float_as_uint(KH[(nt * 8 + g) * KS_STR + kt * 8 + c]);
                bh[1] = __float_as_uint(KH[(nt * 8 + g) * KS_STR + kt * 8 + c + 4]);
                mma8(s[nt], ah, bh);
                mma8(s[nt], al, bh);
            }
        }

        // ---- causal mask (only last two tiles touch the diagonal)
        if (t >= ntiles - 2) {
            int base_col = t * 64;
            int lim0 = PAST + m0 + w * 16 + g;
            int lim1 = lim0 + 8;
#pragma unroll
            for (int nt = 0; nt < 8; nt++) {
                int c0 = base_col + nt * 8 + 2 * c;
                if (c0 > lim0)     s[nt][0] = -1e30f;
                if (c0 + 1 > lim0) s[nt][1] = -1e30f;
                if (c0 > lim1)     s[nt][2] = -1e30f;
                if (c0 + 1 > lim1) s[nt][3] = -1e30f;
            }
        }

        // ---- online softmax (rows g and g+8; reductions over the 4-lane group)
#pragma unroll
        for (int rr = 0; rr < 2; rr++) {
            float mx = -1e30f;
#pragma unroll
            for (int nt = 0; nt < 8; nt++)
                mx = fmaxf(mx, fmaxf(s[nt][2 * rr], s[nt][2 * rr + 1]));
            mx = fmaxf(mx, __shfl_xor_sync(0xffffffffu, mx, 1));
            mx = fmaxf(mx, __shfl_xor_sync(0xffffffffu, mx, 2));
            float mn = fmaxf(mrow[rr], mx);
            float alpha = __expf(mrow[rr] - mn);
            mrow[rr] = mn;
            float ls = 0.f;
#pragma unroll
            for (int nt = 0; nt < 8; nt++) {
                float e0 = __expf(s[nt][2 * rr] - mn);
                float e1 = __expf(s[nt][2 * rr + 1] - mn);
                s[nt][2 * rr] = e0;
                s[nt][2 * rr + 1] = e1;
                ls += e0 + e1;
            }
            ls += __shfl_xor_sync(0xffffffffu, ls, 1);
            ls += __shfl_xor_sync(0xffffffffu, ls, 2);
            lrow[rr] = lrow[rr] * alpha + ls;
#pragma unroll
            for (int dt = 0; dt < 16; dt++) {
                o[dt][2 * rr] *= alpha;
                o[dt][2 * rr + 1] *= alpha;
            }
        }

        // ---- store P to smem as tf32 bit-patterns
        {
            float* p0 = PS + (w * 16 + g) * PS_STR;
            float* p1 = PS + (w * 16 + g + 8) * PS_STR;
#pragma unroll
            for (int nt = 0; nt < 8; nt++) {
                *(float2*)&p0[nt * 8 + 2 * c] = make_float2(
                    f2tf32f(s[nt][0]), f2tf32f(s[nt][1]));
                *(float2*)&p1[nt * 8 + 2 * c] = make_float2(
                    f2tf32f(s[nt][2]), f2tf32f(s[nt][3]));
            }
        }
        __syncwarp();

        // ---- O += P @ V (single tf32), per warp: 16 x 128
        const float* PSw = PS + (w * 16) * PS_STR;
#pragma unroll
        for (int ktv = 0; ktv < 8; ktv++) {
            unsigned a[4];
            a[0] = __float_as_uint(PSw[g * PS_STR + ktv * 8 + c]);
            a[1] = __float_as_uint(PSw[(g + 8) * PS_STR + ktv * 8 + c]);
            a[2] = __float_as_uint(PSw[g * PS_STR + ktv * 8 + c + 4]);
            a[3] = __float_as_uint(PSw[(g + 8) * PS_STR + ktv * 8 + c + 4]);
#pragma unroll
            for (int dt = 0; dt < 16; dt++) {
                unsigned b[2];
                b[0] = __float_as_uint(VT[(ktv * 8 + c) * VS_STR + dt * 8 + g]);
                b[1] = __float_as_uint(VT[(ktv * 8 + c + 4) * VS_STR + dt * 8 + g]);
                mma8(o[dt], a, b);
            }
        }
    }

    // ---- normalize and write [1024][3584], pre-rounded to tf32 for O-proj
#pragma unroll
    for (int rr = 0; rr < 2; rr++) {
        float inv = 1.0f / lrow[rr];
        int row = m0 + w * 16 + g + rr * 8;
        float* dst = Aout + (size_t)row * HID + h * HD;
#pragma unroll
        for (int dt = 0; dt < 16; dt++) {
            *(float2*)&dst[dt * 8 + 2 * c] = make_float2(
                f2tf32f(o[dt][2 * rr] * inv),
                f2tf32f(o[dt][2 * rr + 1] * inv));
        }
    }
}

// ---------------------------------------------------------------------------
// Launch
// ---------------------------------------------------------------------------
extern "C" void kernel_launch(void* const* d_in, const int* in_sizes, int n_in,
                              void* d_out, int out_size) {
    (void)in_sizes; (void)n_in; (void)out_size;
    const float* X  = (const float*)d_in[0];
    const float* kc = (const float*)d_in[1];
    const float* vc = (const float*)d_in[2];
    const float* Wq = (const float*)d_in[3];
    const float* bq = (const float*)d_in[4];
    const float* Wk = (const float*)d_in[5];
    const float* bk = (const float*)d_in[6];
    const float* Wv = (const float*)d_in[7];
    const float* bv = (const float*)d_in[8];
    const float* Wo = (const float*)d_in[9];
    const int*  pos = (const int*)d_in[10];
    float* out = (float*)d_out;

    float *qp, *kp, *vp, *qh, *kf, *vf, *attn;
    cudaGetSymbolAddress((void**)&qp, g_qp);
    cudaGetSymbolAddress((void**)&kp, g_kp);
    cudaGetSymbolAddress((void**)&vp, g_vp);
    cudaGetSymbolAddress((void**)&qh, g_qh);
    cudaGetSymbolAddress((void**)&kf, g_kf);
    cudaGetSymbolAddress((void**)&vf, g_vf);
    cudaGetSymbolAddress((void**)&attn, g_attn);

    static bool attr_set = false;
    if (!attr_set) {
        cudaFuncSetAttribute(qkv_gemm_kernel,
                             cudaFuncAttributeMaxDynamicSharedMemorySize, GEMM_SMEM_BYTES);
        cudaFuncSetAttribute(out_gemm_kernel,
                             cudaFuncAttributeMaxDynamicSharedMemorySize, GEMM_SMEM_BYTES);
        cudaFuncSetAttribute(attn_kernel,
                             cudaFuncAttributeMaxDynamicSharedMemorySize, ATTN_SMEM_BYTES);
        attr_set = true;
    }

    // 1) fused QKV projection (Q,K: tf32x2; V: single tf32)
    qkv_gemm_kernel<<<dim3(36, 8), 256, GEMM_SMEM_BYTES>>>(
        X, Wq, bq, Wk, bk, Wv, bv, qp, kp, vp);

    // 2) KV cache prefix copy (tf32-rounds at write)
    {
        int total = NKV * PAST * HD / 4;
        copy_cache_kernel<<<(total + 255) / 256, 256>>>(kc, vc, kf, vf);
    }

    // 3) RoPE + scatter (K/V written as tf32 bits)
    rope_kernel<<<QLEN, 256>>>(qp, kp, vp, pos, qh, kf, vf);

    // 4) flash attention (R12 geometry, pure-copy K/V tiles)
    attn_kernel<<<dim3(8, NH), 256, ATTN_SMEM_BYTES>>>(qh, kf, vf, attn);

    // 5) output projection (A pre-rounded by attn epilogue; Wo cvt per-use)
    out_gemm_kernel<<<dim3(28, 8), 256, GEMM_SMEM_BYTES>>>(attn, Wo, out);
}